// round 8
// baseline (speedup 1.0000x reference)
#include <cuda_runtime.h>
#include <cuda_bf16.h>
#include <mma.h>
#include <cstdint>
#include <math.h>

using namespace nvcuda;

// Problem shape: B=8192, H=512, M=4096, D=256, k<=32
#define BN 8192
#define MN 4096
#define DN 256
#define MAXK 32
#define NCAND 32
#define CAP 512         // candidate buffer width per row
#define CAPW 500        // writable slots
#define RB 64           // rows per dist2 CTA
#define CCH 128         // cols per chunk
#define NCH (MN / CCH)  // 32 chunks
#define BIGF 3.0e37f

__device__ float g_q[BN * DN];               // exact fp32 q (for rescore)
__device__ __nv_bfloat16 g_qb[BN * DN];      // bf16 q (for WMMA)
__device__ __nv_bfloat16 g_mb[MN * DN];      // bf16 mem (for WMMA)
__device__ float g_msq[MN];                  // exact ||m||^2
__device__ float g_thr[BN];                  // per-row candidate threshold
__device__ float g_sig[BN];                  // per-row dist sigma estimate
__device__ int   g_cnt[BN];                  // per-row candidate count
__device__ float g_cd[(size_t)BN * CAP];     // candidate approx dists
__device__ int   g_ci[(size_t)BN * CAP];     // candidate memory indices

// ---------------------------------------------------------------------------
// Kernel 1: q = h @ Wq + bq  (exact fp32 SGEMM) + bf16 copy of q
// ---------------------------------------------------------------------------
__global__ __launch_bounds__(256, 2)
void qproj_kernel(const float* __restrict__ Hm, const float* __restrict__ Wq,
                  const float* __restrict__ bq, int B, int Hd, int D) {
    __shared__ float As[8][128];
    __shared__ float Bs[8][128];
    const int tid = threadIdx.x;
    const int brow = blockIdx.y * 128, bcol = blockIdx.x * 128;
    const int tx = tid & 15, ty = tid >> 4;
    const int a_row = tid >> 1, a_k = (tid & 1) * 4;
    const int b_k = tid >> 5, b_c = (tid & 31) * 4;
    const float* Ap = Hm + (size_t)(brow + a_row) * Hd + a_k;
    const float* Bp = Wq + (size_t)b_k * D + bcol + b_c;
    float acc[8][8];
#pragma unroll
    for (int i = 0; i < 8; i++)
#pragma unroll
        for (int j = 0; j < 8; j++) acc[i][j] = 0.f;
    for (int k0 = 0; k0 < Hd; k0 += 8) {
        float4 av = *(const float4*)(Ap + k0);
        float4 bv = *(const float4*)(Bp + (size_t)k0 * D);
        __syncthreads();
        As[a_k + 0][a_row] = av.x; As[a_k + 1][a_row] = av.y;
        As[a_k + 2][a_row] = av.z; As[a_k + 3][a_row] = av.w;
        *(float4*)&Bs[b_k][b_c] = bv;
        __syncthreads();
#pragma unroll
        for (int kk = 0; kk < 8; kk++) {
            float ar[8], br[8];
            *(float4*)&ar[0] = *(const float4*)&As[kk][ty * 8];
            *(float4*)&ar[4] = *(const float4*)&As[kk][ty * 8 + 4];
            *(float4*)&br[0] = *(const float4*)&Bs[kk][tx * 8];
            *(float4*)&br[4] = *(const float4*)&Bs[kk][tx * 8 + 4];
#pragma unroll
            for (int i = 0; i < 8; i++)
#pragma unroll
                for (int j = 0; j < 8; j++) acc[i][j] += ar[i] * br[j];
        }
    }
#pragma unroll
    for (int i = 0; i < 8; i++) {
        int r = brow + ty * 8 + i;
#pragma unroll
        for (int j = 0; j < 8; j += 4) {
            int c = bcol + tx * 8 + j;
            float4 o;
            o.x = acc[i][j + 0] + bq[c + 0];
            o.y = acc[i][j + 1] + bq[c + 1];
            o.z = acc[i][j + 2] + bq[c + 2];
            o.w = acc[i][j + 3] + bq[c + 3];
            *(float4*)&g_q[(size_t)r * D + c] = o;
            __nv_bfloat162 p0 = __float22bfloat162_rn(make_float2(o.x, o.y));
            __nv_bfloat162 p1 = __float22bfloat162_rn(make_float2(o.z, o.w));
            uint2 pk; pk.x = *(uint32_t*)&p0; pk.y = *(uint32_t*)&p1;
            *(uint2*)&g_qb[(size_t)r * D + c] = pk;
        }
    }
}

// ---------------------------------------------------------------------------
// msq (exact fp32) + bf16 copy of mem
// ---------------------------------------------------------------------------
__global__ void msq_kernel(const float* __restrict__ Mem, int D) {
    const int r = blockIdx.x;
    const float4* p = (const float4*)(Mem + (size_t)r * D);
    float s = 0.f;
    for (int i = threadIdx.x; i < D / 4; i += 64) {
        float4 v = p[i];
        s += v.x * v.x + v.y * v.y + v.z * v.z + v.w * v.w;
        __nv_bfloat162 p0 = __float22bfloat162_rn(make_float2(v.x, v.y));
        __nv_bfloat162 p1 = __float22bfloat162_rn(make_float2(v.z, v.w));
        uint2 pk; pk.x = *(uint32_t*)&p0; pk.y = *(uint32_t*)&p1;
        *(uint2*)&g_mb[(size_t)r * D + i * 4] = pk;
    }
#pragma unroll
    for (int off = 16; off; off >>= 1) s += __shfl_down_sync(0xffffffffu, s, off);
    __shared__ float ws[2];
    if ((threadIdx.x & 31) == 0) ws[threadIdx.x >> 5] = s;
    __syncthreads();
    if (threadIdx.x == 0) g_msq[r] = ws[0] + ws[1];
}

// ---------------------------------------------------------------------------
// thr_kernel: per row sample stats over first 256 memory slots.
// thr = mean - 2*sigma (true 32nd-of-4096 sits near z=-2.42; E[cand]~93)
// One warp per row, 8 rows per 256-thread CTA.
// ---------------------------------------------------------------------------
__global__ __launch_bounds__(256)
void thr_kernel() {
    __shared__ float sq[8][DN];
    const int wid = threadIdx.x >> 5, lane = threadIdx.x & 31;
    const int r = blockIdx.x * 8 + wid;
    for (int i = lane; i < DN; i += 32)
        sq[wid][i] = __bfloat162float(g_qb[(size_t)r * DN + i]);
    __syncwarp();
    float s1 = 0.f, s2 = 0.f;
#pragma unroll
    for (int j = 0; j < 8; j++) {
        int col = lane + 32 * j;
        const __nv_bfloat162* mp = (const __nv_bfloat162*)(g_mb + (size_t)col * DN);
        float dot = 0.f;
        for (int d = 0; d < DN / 2; d++) {
            float2 mv = __bfloat1622float2(mp[d]);
            dot += sq[wid][2 * d] * mv.x + sq[wid][2 * d + 1] * mv.y;
        }
        float dist = g_msq[col] - 2.f * dot;
        s1 += dist; s2 += dist * dist;
    }
#pragma unroll
    for (int off = 16; off; off >>= 1) {
        s1 += __shfl_down_sync(0xffffffffu, s1, off);
        s2 += __shfl_down_sync(0xffffffffu, s2, off);
    }
    if (lane == 0) {
        float m = s1 * (1.f / 256.f);
        float v = s2 * (1.f / 256.f) - m * m;
        float sig = sqrtf(fmaxf(v, 1e-12f));
        g_thr[r] = m - 2.0f * sig;
        g_sig[r] = sig;
    }
}

// ---------------------------------------------------------------------------
// dist2: one CTA owns RB=64 rows x all 4096 cols. WMMA bf16 GEMM in 32
// column chunks of 128; epilogue pushes dist<thr candidates into per-row
// global buffers via CTA-local shared counters (no global atomics, no
// cross-CTA contention). Pass 2 over band [thr, thr+4*sig) only if a row
// has <32 candidates (probability ~7e-5/row).
// ---------------------------------------------------------------------------
__global__ __launch_bounds__(256)
void dist2_kernel() {
    __shared__ float msq_s[MN];          // 16 KB
    __shared__ float ebuf[8 * 256];      // 8 KB staging (per-warp 16x16)
    __shared__ int   scnt[RB];
    __shared__ float thr_s[RB];
    __shared__ float hi_s[RB];
    __shared__ int   need;
    const int tid = threadIdx.x;
    const int lane = tid & 31, wid = tid >> 5;
    const int warp_m = wid >> 1;         // 0..3 -> 16-row band
    const int warp_n = wid & 1;          // 0..1 -> 64-col band
    const int brow = blockIdx.x * RB;

    for (int i = tid; i < MN; i += 256) msq_s[i] = g_msq[i];
    if (tid < RB) {
        scnt[tid] = 0;
        float t = g_thr[brow + tid];
        thr_s[tid] = t;
        hi_s[tid] = t + 4.f * g_sig[brow + tid];
    }
    if (tid == 0) need = 0;
    __syncthreads();

    float* eb = ebuf + wid * 256;
    const int er = lane >> 1, ec = (lane & 1) * 8;
    const int lr = warp_m * 16 + er;     // local row this lane handles

    for (int pass = 0; pass < 2; pass++) {
        for (int c = 0; c < NCH; c++) {
            wmma::fragment<wmma::accumulator, 16, 16, 16, float> acc[4];
#pragma unroll
            for (int nt = 0; nt < 4; nt++) wmma::fill_fragment(acc[nt], 0.f);

            const __nv_bfloat16* Aw = g_qb + (size_t)(brow + warp_m * 16) * DN;
            const __nv_bfloat16* Bw = g_mb + (size_t)(c * CCH + warp_n * 64) * DN;

#pragma unroll 4
            for (int k = 0; k < DN; k += 16) {
                wmma::fragment<wmma::matrix_a, 16, 16, 16, __nv_bfloat16, wmma::row_major> af;
                wmma::load_matrix_sync(af, Aw + k, DN);
#pragma unroll
                for (int nt = 0; nt < 4; nt++) {
                    wmma::fragment<wmma::matrix_b, 16, 16, 16, __nv_bfloat16, wmma::col_major> bf;
                    wmma::load_matrix_sync(bf, Bw + (size_t)nt * 16 * DN + k, DN);
                    wmma::mma_sync(acc[nt], af, bf, acc[nt]);
                }
            }

            // epilogue: stage each 16x16 frag, push passing candidates
            const int grow = brow + lr;
            const float t_lo = (pass == 0) ? -BIGF : thr_s[lr];
            const float t_hi = (pass == 0) ? thr_s[lr] : hi_s[lr];
#pragma unroll
            for (int nt = 0; nt < 4; nt++) {
                wmma::store_matrix_sync(eb, acc[nt], 16, wmma::mem_row_major);
                __syncwarp();
                const float* e = eb + er * 16 + ec;
#pragma unroll
                for (int jj = 0; jj < 8; jj++) {
                    int col = c * CCH + warp_n * 64 + nt * 16 + ec + jj;
                    float dist = msq_s[col] - 2.f * e[jj];
                    if (dist >= t_lo && dist < t_hi) {
                        int pos = atomicAdd(&scnt[lr], 1);
                        if (pos < CAPW) {
                            g_cd[(size_t)grow * CAP + pos] = dist;
                            g_ci[(size_t)grow * CAP + pos] = col;
                        }
                    }
                }
                __syncwarp();
            }
        }
        __syncthreads();
        if (pass == 0) {
            if (tid < RB && scnt[tid] < NCAND) need = 1;
            __syncthreads();
            if (!need) break;
        }
    }
    if (tid < RB) g_cnt[brow + tid] = scnt[tid];
}

// ---------------------------------------------------------------------------
// topk2: per row, select 32 smallest approx among <=500 candidates (value+
// index tie-break: order-independent), exact fp32 rescore, exact top-k,
// softmax(-dist), weighted gather.
// ---------------------------------------------------------------------------
__global__ __launch_bounds__(128)
void topk2_kernel(const float* __restrict__ Mem, const int* __restrict__ kp,
                  float* __restrict__ out, int M, int D) {
    const int b = blockIdx.x;
    const int tid = threadIdx.x;
    const int wid = tid >> 5, lane = tid & 31;
    int k = kp[0];
    if (k < 1) k = 1;
    if (k > MAXK) k = MAXK;

    __shared__ float scd[CAP];
    __shared__ int sci[CAP];
    __shared__ float sq[DN];
    __shared__ float tval[128];
    __shared__ int tslot[128];
    __shared__ int tcid[128];
    __shared__ int cand[NCAND];
    __shared__ float cdist[NCAND];
    __shared__ float swt[MAXK];
    __shared__ int sel[MAXK];
    __shared__ int swin;

    int cnt = g_cnt[b];
    if (cnt > CAPW) cnt = CAPW;
    for (int i = tid; i < CAP; i += 128) {
        if (i < cnt) { scd[i] = g_cd[(size_t)b * CAP + i]; sci[i] = g_ci[(size_t)b * CAP + i]; }
        else         { scd[i] = BIGF; sci[i] = 0x7FFFFFFF; }
    }
    for (int i = tid; i < D / 4; i += 128)
        ((float4*)sq)[i] = ((const float4*)(g_q + (size_t)b * D))[i];
    __syncthreads();

    // per-thread min over its 4 slots (value, then index: order-independent)
    auto localmin = [&](int t) {
        float bv = BIGF; int bs = t; int bix = 0x7FFFFFFF;
#pragma unroll
        for (int s = 0; s < 4; s++) {
            int sl = t + s * 128;
            float v = scd[sl]; int ix = sci[sl];
            if (v < bv || (v == bv && ix < bix)) { bv = v; bs = sl; bix = ix; }
        }
        tval[t] = bv; tslot[t] = bs; tcid[t] = bix;
    };
    localmin(tid);
    __syncthreads();

    for (int it = 0; it < NCAND; it++) {
        if (tid < 32) {
            float v = tval[tid]; int slot = tid; int ix = tcid[tid];
#pragma unroll
            for (int s = 32; s < 128; s += 32) {
                float v2 = tval[tid + s]; int i2 = tcid[tid + s];
                if (v2 < v || (v2 == v && i2 < ix)) { v = v2; slot = tid + s; ix = i2; }
            }
#pragma unroll
            for (int off = 16; off; off >>= 1) {
                float v2 = __shfl_down_sync(0xffffffffu, v, off);
                int sl2 = __shfl_down_sync(0xffffffffu, slot, off);
                int i2 = __shfl_down_sync(0xffffffffu, ix, off);
                if (v2 < v || (v2 == v && i2 < ix)) { v = v2; slot = sl2; ix = i2; }
            }
            if (tid == 0) { swin = slot; cand[it] = (ix == 0x7FFFFFFF) ? -1 : ix; }
        }
        __syncthreads();
        if (tid == swin) {
            scd[tslot[tid]] = BIGF; sci[tslot[tid]] = 0x7FFFFFFF;
            localmin(tid);
        }
        __syncthreads();
    }

    // exact rescore: dist = msq[c] - 2 * (q . mem_c)  (fp32)
    for (int i = 0; i < 8; i++) {
        int ci = wid * 8 + i;
        int midx = cand[ci];
        if (midx < 0) { if (lane == 0) cdist[ci] = BIGF; continue; }
        const float4* mp = (const float4*)(Mem + (size_t)midx * D + lane * 8);
        float4 m0 = mp[0], m1 = mp[1];
        float4 a0 = *(const float4*)&sq[lane * 8];
        float4 a1 = *(const float4*)&sq[lane * 8 + 4];
        float s = a0.x * m0.x + a0.y * m0.y + a0.z * m0.z + a0.w * m0.w
                + a1.x * m1.x + a1.y * m1.y + a1.z * m1.z + a1.w * m1.w;
#pragma unroll
        for (int off = 16; off; off >>= 1) s += __shfl_down_sync(0xffffffffu, s, off);
        if (lane == 0) cdist[ci] = g_msq[midx] - 2.f * s;
    }
    __syncthreads();

    // exact top-k among 32 rescored candidates (warp 0)
    if (tid < 32) {
        float v = cdist[tid];
        for (int it = 0; it < k; it++) {
            float m = v; int s = tid;
#pragma unroll
            for (int off = 16; off; off >>= 1) {
                float m2 = __shfl_xor_sync(0xffffffffu, m, off);
                int s2 = __shfl_xor_sync(0xffffffffu, s, off);
                if (m2 < m || (m2 == m && s2 < s)) { m = m2; s = s2; }
            }
            if (tid == 0) { swt[it] = m; sel[it] = cand[s]; }
            if (tid == s) v = BIGF;
        }
    }
    __syncthreads();

    if (tid == 0) {
        float d0 = swt[0], ssum = 0.f;
        for (int i = 0; i < k; i++) {
            float e = expf(d0 - swt[i]);
            swt[i] = e; ssum += e;
        }
        float inv = 1.f / ssum;
        for (int i = 0; i < k; i++) swt[i] *= inv;
    }
    __syncthreads();

    for (int d = tid; d < D; d += 128) {
        float acc = 0.f;
        for (int i = 0; i < k; i++)
            acc += swt[i] * Mem[(size_t)sel[i] * D + d];
        out[(size_t)b * D + d] = acc;
    }
}

// ---------------------------------------------------------------------------
extern "C" void kernel_launch(void* const* d_in, const int* in_sizes, int n_in,
                              void* d_out, int out_size) {
    const float* h   = (const float*)d_in[0];
    const float* mem = (const float*)d_in[1];
    const float* Wq  = (const float*)d_in[2];
    const float* bq  = (const float*)d_in[3];
    const int*   kp  = (const int*)d_in[4];
    float* out = (float*)d_out;

    const int D  = in_sizes[3];
    const int Hd = in_sizes[2] / D;
    const int B  = in_sizes[0] / Hd;
    const int M  = in_sizes[1] / D;

    dim3 g1(D / 128, B / 128);
    qproj_kernel<<<g1, 256>>>(h, Wq, bq, B, Hd, D);
    msq_kernel<<<M, 64>>>(mem, D);
    thr_kernel<<<BN / 8, 256>>>();
    dist2_kernel<<<BN / RB, 256>>>();
    topk2_kernel<<<B, 128>>>(mem, kp, out, M, D);
}

// round 9
// speedup vs baseline: 4.2867x; 4.2867x over previous
#include <cuda_runtime.h>
#include <cuda_bf16.h>
#include <cuda_fp16.h>
#include <mma.h>
#include <cstdint>
#include <math.h>

using namespace nvcuda;

// Problem shape: B=8192, H=512, M=4096, D=256, k<=32
#define BN 8192
#define MN 4096
#define DN 256
#define MAXK 32
#define NCAND 32
#define BIGF 3.0e37f

__device__ float g_q[BN * DN];               // exact fp32 q (for rescore)
__device__ __nv_bfloat16 g_qb[BN * DN];      // bf16 q (for WMMA)
__device__ __nv_bfloat16 g_mb[MN * DN];      // bf16 mem (for WMMA)
__device__ float g_msq[MN];                  // exact ||m||^2
__device__ __half g_dist[(size_t)BN * MN];   // 67MB approx dists (selection only)

// ---------------------------------------------------------------------------
// Kernel 1: q = h @ Wq + bq  (exact fp32 SGEMM) + bf16 copy of q
// ---------------------------------------------------------------------------
__global__ __launch_bounds__(256, 2)
void qproj_kernel(const float* __restrict__ Hm, const float* __restrict__ Wq,
                  const float* __restrict__ bq, int B, int Hd, int D) {
    __shared__ float As[8][128];
    __shared__ float Bs[8][128];
    const int tid = threadIdx.x;
    const int brow = blockIdx.y * 128, bcol = blockIdx.x * 128;
    const int tx = tid & 15, ty = tid >> 4;
    const int a_row = tid >> 1, a_k = (tid & 1) * 4;
    const int b_k = tid >> 5, b_c = (tid & 31) * 4;
    const float* Ap = Hm + (size_t)(brow + a_row) * Hd + a_k;
    const float* Bp = Wq + (size_t)b_k * D + bcol + b_c;
    float acc[8][8];
#pragma unroll
    for (int i = 0; i < 8; i++)
#pragma unroll
        for (int j = 0; j < 8; j++) acc[i][j] = 0.f;
    for (int k0 = 0; k0 < Hd; k0 += 8) {
        float4 av = *(const float4*)(Ap + k0);
        float4 bv = *(const float4*)(Bp + (size_t)k0 * D);
        __syncthreads();
        As[a_k + 0][a_row] = av.x; As[a_k + 1][a_row] = av.y;
        As[a_k + 2][a_row] = av.z; As[a_k + 3][a_row] = av.w;
        *(float4*)&Bs[b_k][b_c] = bv;
        __syncthreads();
#pragma unroll
        for (int kk = 0; kk < 8; kk++) {
            float ar[8], br[8];
            *(float4*)&ar[0] = *(const float4*)&As[kk][ty * 8];
            *(float4*)&ar[4] = *(const float4*)&As[kk][ty * 8 + 4];
            *(float4*)&br[0] = *(const float4*)&Bs[kk][tx * 8];
            *(float4*)&br[4] = *(const float4*)&Bs[kk][tx * 8 + 4];
#pragma unroll
            for (int i = 0; i < 8; i++)
#pragma unroll
                for (int j = 0; j < 8; j++) acc[i][j] += ar[i] * br[j];
        }
    }
#pragma unroll
    for (int i = 0; i < 8; i++) {
        int r = brow + ty * 8 + i;
#pragma unroll
        for (int j = 0; j < 8; j += 4) {
            int c = bcol + tx * 8 + j;
            float4 o;
            o.x = acc[i][j + 0] + bq[c + 0];
            o.y = acc[i][j + 1] + bq[c + 1];
            o.z = acc[i][j + 2] + bq[c + 2];
            o.w = acc[i][j + 3] + bq[c + 3];
            *(float4*)&g_q[(size_t)r * D + c] = o;
            __nv_bfloat162 p0 = __float22bfloat162_rn(make_float2(o.x, o.y));
            __nv_bfloat162 p1 = __float22bfloat162_rn(make_float2(o.z, o.w));
            uint2 pk; pk.x = *(uint32_t*)&p0; pk.y = *(uint32_t*)&p1;
            *(uint2*)&g_qb[(size_t)r * D + c] = pk;
        }
    }
}

// ---------------------------------------------------------------------------
// msq (exact fp32) + bf16 copy of mem
// ---------------------------------------------------------------------------
__global__ void msq_kernel(const float* __restrict__ Mem, int D) {
    const int r = blockIdx.x;
    const float4* p = (const float4*)(Mem + (size_t)r * D);
    float s = 0.f;
    for (int i = threadIdx.x; i < D / 4; i += 64) {
        float4 v = p[i];
        s += v.x * v.x + v.y * v.y + v.z * v.z + v.w * v.w;
        __nv_bfloat162 p0 = __float22bfloat162_rn(make_float2(v.x, v.y));
        __nv_bfloat162 p1 = __float22bfloat162_rn(make_float2(v.z, v.w));
        uint2 pk; pk.x = *(uint32_t*)&p0; pk.y = *(uint32_t*)&p1;
        *(uint2*)&g_mb[(size_t)r * D + i * 4] = pk;
    }
#pragma unroll
    for (int off = 16; off; off >>= 1) s += __shfl_down_sync(0xffffffffu, s, off);
    __shared__ float ws[2];
    if ((threadIdx.x & 31) == 0) ws[threadIdx.x >> 5] = s;
    __syncthreads();
    if (threadIdx.x == 0) g_msq[r] = ws[0] + ws[1];
}

// ---------------------------------------------------------------------------
// Kernel 3: dist[b,m] ~= msq[m] - 2*(q_b . mem_m) via WMMA bf16.
// CTA 128x128, 8 warps (2 m x 4 n), warp tile 64x32 = 4x2 wmma 16x16x16.
// Output stored as fp16 (selection-only; exact rescore follows).
// ---------------------------------------------------------------------------
__global__ __launch_bounds__(256, 2)
void dist_wmma_kernel(int B, int M, int D) {
    __shared__ float ebuf[8 * 256];   // per-warp 16x16 epilogue staging (8KB)
    __shared__ float msq_s[128];
    const int tid = threadIdx.x;
    const int lane = tid & 31, wid = tid >> 5;
    const int warp_m = wid >> 2, warp_n = wid & 3;     // 2 x 4
    const int brow = blockIdx.y * 128;                  // B rows
    const int bcol = blockIdx.x * 128;                  // M cols

    if (tid < 128) msq_s[tid] = g_msq[bcol + tid];
    __syncthreads();

    wmma::fragment<wmma::accumulator, 16, 16, 16, float> acc[4][2];
#pragma unroll
    for (int mt = 0; mt < 4; mt++)
#pragma unroll
        for (int nt = 0; nt < 2; nt++) wmma::fill_fragment(acc[mt][nt], 0.f);

    const __nv_bfloat16* Aw = g_qb + (size_t)(brow + warp_m * 64) * DN;
    const __nv_bfloat16* Bw = g_mb + (size_t)(bcol + warp_n * 32) * DN;

    for (int k = 0; k < DN; k += 16) {
        wmma::fragment<wmma::matrix_a, 16, 16, 16, __nv_bfloat16, wmma::row_major> af[4];
        wmma::fragment<wmma::matrix_b, 16, 16, 16, __nv_bfloat16, wmma::col_major> bf[2];
#pragma unroll
        for (int mt = 0; mt < 4; mt++)
            wmma::load_matrix_sync(af[mt], Aw + (size_t)mt * 16 * DN + k, DN);
#pragma unroll
        for (int nt = 0; nt < 2; nt++)
            wmma::load_matrix_sync(bf[nt], Bw + (size_t)nt * 16 * DN + k, DN);
#pragma unroll
        for (int mt = 0; mt < 4; mt++)
#pragma unroll
            for (int nt = 0; nt < 2; nt++)
                wmma::mma_sync(acc[mt][nt], af[mt], bf[nt], acc[mt][nt]);
    }

    // epilogue: stage each 16x16 frag through smem, apply msq[m] - 2*acc,
    // pack 8 fp16 and store as one uint4
    float* eb = ebuf + wid * 256;
    const int er = lane >> 1, ec = (lane & 1) * 8;
#pragma unroll
    for (int mt = 0; mt < 4; mt++) {
#pragma unroll
        for (int nt = 0; nt < 2; nt++) {
            wmma::store_matrix_sync(eb, acc[mt][nt], 16, wmma::mem_row_major);
            __syncwarp();
            int grow = brow + warp_m * 64 + mt * 16 + er;
            int cl = warp_n * 32 + nt * 16 + ec;      // local col in [0,128)
            const float* e = eb + er * 16 + ec;
            __half2 h0 = __floats2half2_rn(msq_s[cl + 0] - 2.f * e[0],
                                           msq_s[cl + 1] - 2.f * e[1]);
            __half2 h1 = __floats2half2_rn(msq_s[cl + 2] - 2.f * e[2],
                                           msq_s[cl + 3] - 2.f * e[3]);
            __half2 h2 = __floats2half2_rn(msq_s[cl + 4] - 2.f * e[4],
                                           msq_s[cl + 5] - 2.f * e[5]);
            __half2 h3 = __floats2half2_rn(msq_s[cl + 6] - 2.f * e[6],
                                           msq_s[cl + 7] - 2.f * e[7]);
            uint4 pk;
            pk.x = *(uint32_t*)&h0; pk.y = *(uint32_t*)&h1;
            pk.z = *(uint32_t*)&h2; pk.w = *(uint32_t*)&h3;
            *(uint4*)&g_dist[(size_t)grow * M + bcol + cl] = pk;
            __syncwarp();
        }
    }
}

// ---------------------------------------------------------------------------
// Kernel 4: approx top-32 (fp16 dists) -> exact fp32 rescore -> exact top-k
// -> softmax(-dist) -> weighted gather. One 128-thread block per row.
// ---------------------------------------------------------------------------
__global__ __launch_bounds__(128)
void topk_kernel(const float* __restrict__ Mem, const int* __restrict__ kp,
                 float* __restrict__ out, int M, int D) {
    const int b = blockIdx.x;
    const int tid = threadIdx.x;
    const int wid = tid >> 5, lane = tid & 31;
    int k = kp[0];
    if (k < 1) k = 1;
    if (k > NCAND) k = NCAND;

    __shared__ float sd[MN];
    __shared__ float sq[DN];
    __shared__ float tval[128];
    __shared__ int tidxs[128];
    __shared__ int cand[NCAND];
    __shared__ float cdist[NCAND];
    __shared__ float swt[MAXK];
    __shared__ int sel[MAXK];
    __shared__ int swin;

    // load fp16 row, convert to fp32 in smem (8 halves per uint4)
    const uint4* rp = (const uint4*)(g_dist + (size_t)b * M);
    for (int i = tid; i < M / 8; i += 128) {
        uint4 pk = rp[i];
        float2 f0 = __half22float2(*(__half2*)&pk.x);
        float2 f1 = __half22float2(*(__half2*)&pk.y);
        float2 f2 = __half22float2(*(__half2*)&pk.z);
        float2 f3 = __half22float2(*(__half2*)&pk.w);
        float4 o0 = make_float4(f0.x, f0.y, f1.x, f1.y);
        float4 o1 = make_float4(f2.x, f2.y, f3.x, f3.y);
        *(float4*)&sd[i * 8] = o0;
        *(float4*)&sd[i * 8 + 4] = o1;
    }
    for (int i = tid; i < D / 4; i += 128)
        ((float4*)sq)[i] = ((const float4*)(g_q + (size_t)b * D))[i];
    __syncthreads();

    float bv = BIGF; int bi = -1;
    for (int i = tid; i < M; i += 128) {
        float v = sd[i];
        if (v < bv) { bv = v; bi = i; }
    }
    tval[tid] = bv; tidxs[tid] = bi;
    __syncthreads();
    for (int it = 0; it < NCAND; it++) {
        if (tid < 32) {
            float v = tval[tid]; int slot = tid;
#pragma unroll
            for (int s = 32; s < 128; s += 32) {
                float v2 = tval[tid + s];
                if (v2 < v) { v = v2; slot = tid + s; }
            }
#pragma unroll
            for (int off = 16; off; off >>= 1) {
                float v2 = __shfl_down_sync(0xffffffffu, v, off);
                int sl2 = __shfl_down_sync(0xffffffffu, slot, off);
                if (v2 < v) { v = v2; slot = sl2; }
            }
            if (tid == 0) { swin = slot; cand[it] = tidxs[slot]; }
        }
        __syncthreads();
        if (tid == swin && tidxs[tid] >= 0) {
            sd[tidxs[tid]] = BIGF;
            float nv = BIGF; int ni = -1;
            for (int i = tid; i < M; i += 128) {
                float v = sd[i];
                if (v < nv) { nv = v; ni = i; }
            }
            tval[tid] = nv; tidxs[tid] = ni;
        }
        __syncthreads();
    }

    // exact rescore: dist = msq[c] - 2 * (q . mem_c)  (fp32)
    for (int i = 0; i < 8; i++) {
        int ci = wid * 8 + i;
        int midx = cand[ci];
        if (midx < 0) { if (lane == 0) cdist[ci] = BIGF; continue; }
        const float4* mp = (const float4*)(Mem + (size_t)midx * D + lane * 8);
        float4 m0 = mp[0], m1 = mp[1];
        float4 a0 = *(const float4*)&sq[lane * 8];
        float4 a1 = *(const float4*)&sq[lane * 8 + 4];
        float s = a0.x * m0.x + a0.y * m0.y + a0.z * m0.z + a0.w * m0.w
                + a1.x * m1.x + a1.y * m1.y + a1.z * m1.z + a1.w * m1.w;
#pragma unroll
        for (int off = 16; off; off >>= 1) s += __shfl_down_sync(0xffffffffu, s, off);
        if (lane == 0) cdist[ci] = g_msq[midx] - 2.f * s;
    }
    __syncthreads();

    if (tid < 32) {
        float v = cdist[tid];
        for (int it = 0; it < k; it++) {
            float m = v; int s = tid;
#pragma unroll
            for (int off = 16; off; off >>= 1) {
                float m2 = __shfl_xor_sync(0xffffffffu, m, off);
                int s2 = __shfl_xor_sync(0xffffffffu, s, off);
                if (m2 < m || (m2 == m && s2 < s)) { m = m2; s = s2; }
            }
            if (tid == 0) { swt[it] = m; sel[it] = cand[s]; }
            if (tid == s) v = BIGF;
        }
    }
    __syncthreads();

    if (tid == 0) {
        float d0 = swt[0], ssum = 0.f;
        for (int i = 0; i < k; i++) {
            float e = expf(d0 - swt[i]);
            swt[i] = e; ssum += e;
        }
        float inv = 1.f / ssum;
        for (int i = 0; i < k; i++) swt[i] *= inv;
    }
    __syncthreads();

    for (int d = tid; d < D; d += 128) {
        float acc = 0.f;
        for (int i = 0; i < k; i++)
            acc += swt[i] * Mem[(size_t)sel[i] * D + d];
        out[(size_t)b * D + d] = acc;
    }
}

// ---------------------------------------------------------------------------
extern "C" void kernel_launch(void* const* d_in, const int* in_sizes, int n_in,
                              void* d_out, int out_size) {
    const float* h   = (const float*)d_in[0];
    const float* mem = (const float*)d_in[1];
    const float* Wq  = (const float*)d_in[2];
    const float* bq  = (const float*)d_in[3];
    const int*   kp  = (const int*)d_in[4];
    float* out = (float*)d_out;

    const int D  = in_sizes[3];
    const int Hd = in_sizes[2] / D;
    const int B  = in_sizes[0] / Hd;
    const int M  = in_sizes[1] / D;

    dim3 g1(D / 128, B / 128);
    qproj_kernel<<<g1, 256>>>(h, Wq, bq, B, Hd, D);
    msq_kernel<<<M, 64>>>(mem, D);
    dim3 g3(M / 128, B / 128);
    dist_wmma_kernel<<<g3, 256>>>(B, M, D);
    topk_kernel<<<B, 128>>>(mem, kp, out, M, D);
}

// round 11
// speedup vs baseline: 6.5109x; 1.5189x over previous
#include <cuda_runtime.h>
#include <cuda_bf16.h>
#include <cuda_fp16.h>
#include <mma.h>
#include <cstdint>
#include <math.h>

using namespace nvcuda;

// Problem shape: B=8192, H=512, M=4096, D=256, k<=32
#define BN 8192
#define MN 4096
#define DN 256
#define MAXK 32
#define NCAND 32
#define RPB 4           // rows per topk block
#define CAPB 512        // candidate slots per row (overflow now ~7 sigma out)
#define BIGF 3.0e37f

__device__ float g_q[BN * DN];               // exact fp32 q (for rescore)
__device__ __nv_bfloat16 g_qb[BN * DN];      // bf16 q (for WMMA)
__device__ __nv_bfloat16 g_mb[MN * DN];      // bf16 mem (for WMMA)
__device__ float g_msq[MN];                  // exact ||m||^2
__device__ __half g_dist[(size_t)BN * MN];   // 67MB approx dists (selection only)

// ---------------------------------------------------------------------------
// Kernel 1: q = h @ Wq + bq  (exact fp32 SGEMM) + bf16 copy of q
// ---------------------------------------------------------------------------
__global__ __launch_bounds__(256, 2)
void qproj_kernel(const float* __restrict__ Hm, const float* __restrict__ Wq,
                  const float* __restrict__ bq, int B, int Hd, int D) {
    __shared__ float As[8][128];
    __shared__ float Bs[8][128];
    const int tid = threadIdx.x;
    const int brow = blockIdx.y * 128, bcol = blockIdx.x * 128;
    const int tx = tid & 15, ty = tid >> 4;
    const int a_row = tid >> 1, a_k = (tid & 1) * 4;
    const int b_k = tid >> 5, b_c = (tid & 31) * 4;
    const float* Ap = Hm + (size_t)(brow + a_row) * Hd + a_k;
    const float* Bp = Wq + (size_t)b_k * D + bcol + b_c;
    float acc[8][8];
#pragma unroll
    for (int i = 0; i < 8; i++)
#pragma unroll
        for (int j = 0; j < 8; j++) acc[i][j] = 0.f;
    for (int k0 = 0; k0 < Hd; k0 += 8) {
        float4 av = *(const float4*)(Ap + k0);
        float4 bv = *(const float4*)(Bp + (size_t)k0 * D);
        __syncthreads();
        As[a_k + 0][a_row] = av.x; As[a_k + 1][a_row] = av.y;
        As[a_k + 2][a_row] = av.z; As[a_k + 3][a_row] = av.w;
        *(float4*)&Bs[b_k][b_c] = bv;
        __syncthreads();
#pragma unroll
        for (int kk = 0; kk < 8; kk++) {
            float ar[8], br[8];
            *(float4*)&ar[0] = *(const float4*)&As[kk][ty * 8];
            *(float4*)&ar[4] = *(const float4*)&As[kk][ty * 8 + 4];
            *(float4*)&br[0] = *(const float4*)&Bs[kk][tx * 8];
            *(float4*)&br[4] = *(const float4*)&Bs[kk][tx * 8 + 4];
#pragma unroll
            for (int i = 0; i < 8; i++)
#pragma unroll
                for (int j = 0; j < 8; j++) acc[i][j] += ar[i] * br[j];
        }
    }
#pragma unroll
    for (int i = 0; i < 8; i++) {
        int r = brow + ty * 8 + i;
#pragma unroll
        for (int j = 0; j < 8; j += 4) {
            int c = bcol + tx * 8 + j;
            float4 o;
            o.x = acc[i][j + 0] + bq[c + 0];
            o.y = acc[i][j + 1] + bq[c + 1];
            o.z = acc[i][j + 2] + bq[c + 2];
            o.w = acc[i][j + 3] + bq[c + 3];
            *(float4*)&g_q[(size_t)r * D + c] = o;
            __nv_bfloat162 p0 = __float22bfloat162_rn(make_float2(o.x, o.y));
            __nv_bfloat162 p1 = __float22bfloat162_rn(make_float2(o.z, o.w));
            uint2 pk; pk.x = *(uint32_t*)&p0; pk.y = *(uint32_t*)&p1;
            *(uint2*)&g_qb[(size_t)r * D + c] = pk;
        }
    }
}

// ---------------------------------------------------------------------------
// msq (exact fp32) + bf16 copy of mem
// ---------------------------------------------------------------------------
__global__ void msq_kernel(const float* __restrict__ Mem, int D) {
    const int r = blockIdx.x;
    const float4* p = (const float4*)(Mem + (size_t)r * D);
    float s = 0.f;
    for (int i = threadIdx.x; i < D / 4; i += 64) {
        float4 v = p[i];
        s += v.x * v.x + v.y * v.y + v.z * v.z + v.w * v.w;
        __nv_bfloat162 p0 = __float22bfloat162_rn(make_float2(v.x, v.y));
        __nv_bfloat162 p1 = __float22bfloat162_rn(make_float2(v.z, v.w));
        uint2 pk; pk.x = *(uint32_t*)&p0; pk.y = *(uint32_t*)&p1;
        *(uint2*)&g_mb[(size_t)r * D + i * 4] = pk;
    }
#pragma unroll
    for (int off = 16; off; off >>= 1) s += __shfl_down_sync(0xffffffffu, s, off);
    __shared__ float ws[2];
    if ((threadIdx.x & 31) == 0) ws[threadIdx.x >> 5] = s;
    __syncthreads();
    if (threadIdx.x == 0) g_msq[r] = ws[0] + ws[1];
}

// ---------------------------------------------------------------------------
// Kernel 3: dist = msq[m] - 2*(q.m) via WMMA bf16 with SMEM-staged tiles.
// CTA 128x128, 8 warps (2x4), warp 64x32. K=256 in 8 chunks of 32.
// Register-prefetch next chunk during compute. fp16 output.
// ---------------------------------------------------------------------------
#define ASTRIDE 40      // halves per smem row (80B, 16B-aligned rows)

__global__ __launch_bounds__(256, 2)
void dist_wmma_kernel(int B, int M, int D) {
    __shared__ __nv_bfloat16 As[128 * ASTRIDE];   // 10240 B
    __shared__ __nv_bfloat16 Bs[128 * ASTRIDE];   // 10240 B
    __shared__ float ebuf[8 * 256];               // 8 KB
    __shared__ float msq_s[128];
    const int tid = threadIdx.x;
    const int lane = tid & 31, wid = tid >> 5;
    const int warp_m = wid >> 2, warp_n = wid & 3;     // 2 x 4
    const int brow = blockIdx.y * 128;
    const int bcol = blockIdx.x * 128;

    if (tid < 128) msq_s[tid] = g_msq[bcol + tid];

    const __nv_bfloat16* Ag = g_qb + (size_t)brow * DN;
    const __nv_bfloat16* Bg = g_mb + (size_t)bcol * DN;

    const int r0 = tid >> 2, q0 = (tid & 3) * 8;
    const int r1 = r0 + 64, q1 = q0;

    uint4 ra0, ra1, rb0, rb1;
    ra0 = *(const uint4*)(Ag + (size_t)r0 * DN + q0);
    ra1 = *(const uint4*)(Ag + (size_t)r1 * DN + q1);
    rb0 = *(const uint4*)(Bg + (size_t)r0 * DN + q0);
    rb1 = *(const uint4*)(Bg + (size_t)r1 * DN + q1);

    wmma::fragment<wmma::accumulator, 16, 16, 16, float> acc[4][2];
#pragma unroll
    for (int mt = 0; mt < 4; mt++)
#pragma unroll
        for (int nt = 0; nt < 2; nt++) wmma::fill_fragment(acc[mt][nt], 0.f);

    for (int c = 0; c < 8; c++) {
        __syncthreads();
        *(uint4*)(As + r0 * ASTRIDE + q0) = ra0;
        *(uint4*)(As + r1 * ASTRIDE + q1) = ra1;
        *(uint4*)(Bs + r0 * ASTRIDE + q0) = rb0;
        *(uint4*)(Bs + r1 * ASTRIDE + q1) = rb1;
        if (c < 7) {
            int kb = (c + 1) * 32;
            ra0 = *(const uint4*)(Ag + (size_t)r0 * DN + kb + q0);
            ra1 = *(const uint4*)(Ag + (size_t)r1 * DN + kb + q1);
            rb0 = *(const uint4*)(Bg + (size_t)r0 * DN + kb + q0);
            rb1 = *(const uint4*)(Bg + (size_t)r1 * DN + kb + q1);
        }
        __syncthreads();

#pragma unroll
        for (int ks = 0; ks < 2; ks++) {
            wmma::fragment<wmma::matrix_b, 16, 16, 16, __nv_bfloat16, wmma::col_major> bf[2];
#pragma unroll
            for (int nt = 0; nt < 2; nt++)
                wmma::load_matrix_sync(bf[nt],
                    Bs + (warp_n * 32 + nt * 16) * ASTRIDE + ks * 16, ASTRIDE);
#pragma unroll
            for (int mt = 0; mt < 4; mt++) {
                wmma::fragment<wmma::matrix_a, 16, 16, 16, __nv_bfloat16, wmma::row_major> af;
                wmma::load_matrix_sync(af,
                    As + (warp_m * 64 + mt * 16) * ASTRIDE + ks * 16, ASTRIDE);
#pragma unroll
                for (int nt = 0; nt < 2; nt++)
                    wmma::mma_sync(acc[mt][nt], af, bf[nt], acc[mt][nt]);
            }
        }
    }

    float* eb = ebuf + wid * 256;
    const int er = lane >> 1, ec = (lane & 1) * 8;
#pragma unroll
    for (int mt = 0; mt < 4; mt++) {
#pragma unroll
        for (int nt = 0; nt < 2; nt++) {
            wmma::store_matrix_sync(eb, acc[mt][nt], 16, wmma::mem_row_major);
            __syncwarp();
            int grow = brow + warp_m * 64 + mt * 16 + er;
            int cl = warp_n * 32 + nt * 16 + ec;
            const float* e = eb + er * 16 + ec;
            __half2 h0 = __floats2half2_rn(msq_s[cl + 0] - 2.f * e[0],
                                           msq_s[cl + 1] - 2.f * e[1]);
            __half2 h1 = __floats2half2_rn(msq_s[cl + 2] - 2.f * e[2],
                                           msq_s[cl + 3] - 2.f * e[3]);
            __half2 h2 = __floats2half2_rn(msq_s[cl + 4] - 2.f * e[4],
                                           msq_s[cl + 5] - 2.f * e[5]);
            __half2 h3 = __floats2half2_rn(msq_s[cl + 6] - 2.f * e[6],
                                           msq_s[cl + 7] - 2.f * e[7]);
            uint4 pk;
            pk.x = *(uint32_t*)&h0; pk.y = *(uint32_t*)&h1;
            pk.z = *(uint32_t*)&h2; pk.w = *(uint32_t*)&h3;
            *(uint4*)&g_dist[(size_t)grow * M + bcol + cl] = pk;
            __syncwarp();
        }
    }
}

// ---------------------------------------------------------------------------
// Kernel 4: warp-per-row. Sample stats -> threshold filter with BOTH-SIDED
// retry (accepted only when NCAND<=cnt<=CAPB: set is threshold-defined ->
// deterministic, nothing dropped) -> top-32 via __reduce_min_sync -> exact
// fp32 rescore -> exact top-k -> softmax -> gather. 4 rows/block.
// ---------------------------------------------------------------------------
__global__ __launch_bounds__(128)
void topk_kernel(const float* __restrict__ Mem, const int* __restrict__ kp,
                 float* __restrict__ out, int M, int D) {
    __shared__ __half sh_d[RPB * MN];        // 32 KB
    __shared__ float sh_q[RPB * DN];         // 4 KB
    __shared__ uint32_t ckey[RPB][CAPB];     // 8 KB
    __shared__ int ccnt[RPB];
    __shared__ int scand[RPB][NCAND];
    __shared__ float cd[RPB][NCAND];
    __shared__ float swt[RPB][MAXK];
    __shared__ int ssel[RPB][MAXK];

    const int tid = threadIdx.x, lane = tid & 31, w = tid >> 5;
    const int b0 = blockIdx.x * RPB;
    int k = kp[0];
    if (k < 1) k = 1;
    if (k > MAXK) k = MAXK;

    // Phase A: block-copy 4 contiguous dist rows + 4 q rows
    {
        const uint4* dsrc = (const uint4*)(g_dist + (size_t)b0 * M);
        uint4* ddst = (uint4*)sh_d;
        for (int i = tid; i < RPB * MN / 8; i += 128) ddst[i] = dsrc[i];
        const float4* qsrc = (const float4*)(g_q + (size_t)b0 * DN);
        float4* qdst = (float4*)sh_q;
        for (int i = tid; i < RPB * DN / 4; i += 128) qdst[i] = qsrc[i];
    }
    __syncthreads();

    const __half* drow = sh_d + w * MN;

    // Phase B: per-warp sample stats (256 elems) -> thr = mu - 2*sigma
    float s1 = 0.f, s2 = 0.f;
    {
        const __half2* p = (const __half2*)(drow + lane * 128);
#pragma unroll
        for (int e = 0; e < 4; e++) {
            float2 f = __half22float2(p[e]);
            s1 += f.x + f.y; s2 += f.x * f.x + f.y * f.y;
        }
    }
#pragma unroll
    for (int off = 16; off; off >>= 1) {
        s1 += __shfl_xor_sync(0xffffffffu, s1, off);
        s2 += __shfl_xor_sync(0xffffffffu, s2, off);
    }
    float mu = s1 * (1.f / 256.f);
    float sg = sqrtf(fmaxf(s2 * (1.f / 256.f) - mu * mu, 0.f));
    sg = fmaxf(sg, fabsf(mu) * 1e-4f + 1e-6f);
    float thr = mu - 2.f * sg;

    // Phase C: threshold filter. Accept only NCAND<=cnt<=CAPB; else step
    // +-0.5*sigma (window [32,512] spans ~1.2 sigma -> cannot be stepped over).
    int cnt = 0;
    for (int attempt = 0; attempt < 10; attempt++) {
        __half thrh = __float2half_ru(thr);
        if (lane == 0) ccnt[w] = 0;
        __syncwarp();
        for (int j = 0; j < 16; j++) {
            int gi = j * 32 + lane;                      // uint4 index in row
            uint4 pk = ((const uint4*)drow)[gi];
            __half2 a = *(__half2*)&pk.x, b = *(__half2*)&pk.y;
            __half2 c2 = *(__half2*)&pk.z, d2 = *(__half2*)&pk.w;
            __half2 m2 = __hmin2(__hmin2(a, b), __hmin2(c2, d2));
            __half mn = __hmin(__low2half(m2), __high2half(m2));
            if (__hlt(mn, thrh)) {
                const __half* hp = (const __half*)&pk;
                int base = gi * 8;
#pragma unroll
                for (int e = 0; e < 8; e++) {
                    __half h = hp[e];
                    if (__hlt(h, thrh)) {
                        unsigned short ub = __half_as_ushort(h);
                        uint32_t o = (ub & 0x8000u) ? (uint32_t)((~ub) & 0xFFFFu)
                                                    : (uint32_t)(ub | 0x8000u);
                        uint32_t key = (o << 12) | (uint32_t)(base + e);
                        int pos = atomicAdd(&ccnt[w], 1);
                        if (pos < CAPB) ckey[w][pos] = key;
                    }
                }
            }
        }
        __syncwarp();
        cnt = ccnt[w];
        if (cnt >= NCAND && cnt <= CAPB) break;
        thr += (cnt < NCAND) ? 0.5f * sg : -0.5f * sg;
        __syncwarp();
    }
    if (cnt > CAPB) cnt = CAPB;    // last-resort clamp (unreachable for sane data)

    // Phase D: top-32 keys via warp redux (keys unique -> deterministic)
    {
        uint32_t lv[CAPB / 32];
#pragma unroll
        for (int j = 0; j < CAPB / 32; j++) {
            int s = lane + 32 * j;
            lv[j] = (s < cnt) ? ckey[w][s] : 0xFFFFFFFFu;
        }
        uint32_t lmin = 0xFFFFFFFFu;
#pragma unroll
        for (int j = 0; j < CAPB / 32; j++) lmin = min(lmin, lv[j]);
        for (int it = 0; it < NCAND; it++) {
            uint32_t g = __reduce_min_sync(0xffffffffu, lmin);
            if (lane == 0) scand[w][it] = (int)(g & 0xFFFu);
            unsigned bal = __ballot_sync(0xffffffffu, lmin == g);
            int wl = __ffs((int)bal) - 1;
            if (lane == wl) {
#pragma unroll
                for (int j = 0; j < CAPB / 32; j++)
                    if (lv[j] == g) lv[j] = 0xFFFFFFFFu;
                lmin = 0xFFFFFFFFu;
#pragma unroll
                for (int j = 0; j < CAPB / 32; j++) lmin = min(lmin, lv[j]);
            }
        }
    }
    __syncthreads();

    // Phase E: exact rescore — one candidate per thread (serial 256-dot)
    {
        int midx = scand[w][lane];
        const float4* mp = (const float4*)(Mem + (size_t)midx * DN);
        const float4* qp = (const float4*)(sh_q + w * DN);
        float dot = 0.f;
#pragma unroll 8
        for (int i = 0; i < 64; i++) {
            float4 a = qp[i], bb = mp[i];
            dot += a.x * bb.x + a.y * bb.y + a.z * bb.z + a.w * bb.w;
        }
        cd[w][lane] = g_msq[midx] - 2.f * dot;
    }
    __syncwarp();

    // Phase F: exact top-k among 32, softmax(-dist), weighted gather
    {
        float v = cd[w][lane];
        for (int it = 0; it < k; it++) {
            float m = v; int s = lane;
#pragma unroll
            for (int off = 16; off; off >>= 1) {
                float m2 = __shfl_xor_sync(0xffffffffu, m, off);
                int s2 = __shfl_xor_sync(0xffffffffu, s, off);
                if (m2 < m || (m2 == m && s2 < s)) { m = m2; s = s2; }
            }
            if (lane == 0) { swt[w][it] = m; ssel[w][it] = scand[w][s]; }
            if (lane == s) v = BIGF;
        }
        __syncwarp();
        if (lane == 0) {
            float d0 = swt[w][0], ssum = 0.f;
            for (int i = 0; i < k; i++) {
                float e = expf(d0 - swt[w][i]);
                swt[w][i] = e; ssum += e;
            }
            float inv = 1.f / ssum;
            for (int i = 0; i < k; i++) swt[w][i] *= inv;
        }
        __syncwarp();

        const int d0 = lane * 8;
        float acc[8];
#pragma unroll
        for (int e = 0; e < 8; e++) acc[e] = 0.f;
        for (int i = 0; i < k; i++) {
            float wt = swt[w][i];
            const float4* mp = (const float4*)(Mem + (size_t)ssel[w][i] * DN + d0);
            float4 a = mp[0], bb = mp[1];
            acc[0] += wt * a.x;  acc[1] += wt * a.y;
            acc[2] += wt * a.z;  acc[3] += wt * a.w;
            acc[4] += wt * bb.x; acc[5] += wt * bb.y;
            acc[6] += wt * bb.z; acc[7] += wt * bb.w;
        }
        float4 o0 = make_float4(acc[0], acc[1], acc[2], acc[3]);
        float4 o1 = make_float4(acc[4], acc[5], acc[6], acc[7]);
        *(float4*)&out[(size_t)(b0 + w) * DN + d0] = o0;
        *(float4*)&out[(size_t)(b0 + w) * DN + d0 + 4] = o1;
    }
}

// ---------------------------------------------------------------------------
extern "C" void kernel_launch(void* const* d_in, const int* in_sizes, int n_in,
                              void* d_out, int out_size) {
    const float* h   = (const float*)d_in[0];
    const float* mem = (const float*)d_in[1];
    const float* Wq  = (const float*)d_in[2];
    const float* bq  = (const float*)d_in[3];
    const int*   kp  = (const int*)d_in[4];
    float* out = (float*)d_out;

    const int D  = in_sizes[3];
    const int Hd = in_sizes[2] / D;
    const int B  = in_sizes[0] / Hd;
    const int M  = in_sizes[1] / D;

    dim3 g1(D / 128, B / 128);
    qproj_kernel<<<g1, 256>>>(h, Wq, bq, B, Hd, D);
    msq_kernel<<<M, 64>>>(mem, D);
    dim3 g3(M / 128, B / 128);
    dist_wmma_kernel<<<g3, 256>>>(B, M, D);
    topk_kernel<<<B / RPB, 128>>>(mem, kp, out, M, D);
}

// round 12
// speedup vs baseline: 7.1921x; 1.1046x over previous
#include <cuda_runtime.h>
#include <cuda_bf16.h>
#include <cuda_fp16.h>
#include <mma.h>
#include <cstdint>
#include <math.h>

using namespace nvcuda;

// Problem shape: B=8192, H=512, M=4096, D=256, k<=32
#define BN 8192
#define MN 4096
#define DN 256
#define MAXK 32
#define NCAND 32
#define RPB 4           // rows per topk block
#define CAPB 512        // candidate slots per row
#define BIGF 3.0e37f

__device__ float g_q[BN * DN];               // exact fp32 q (for rescore)
__device__ __nv_bfloat16 g_qb[BN * DN];      // bf16 q (for WMMA)
__device__ __nv_bfloat16 g_mb[MN * DN];      // bf16 mem (for WMMA)
__device__ float g_msq[MN];                  // exact ||m||^2
__device__ __half g_dist[(size_t)BN * MN];   // 67MB approx dists (selection only)

// ---------------------------------------------------------------------------
// Kernel 1: q = h @ Wq + bq  (exact fp32 SGEMM) + bf16 copy of q
// ---------------------------------------------------------------------------
__global__ __launch_bounds__(256, 2)
void qproj_kernel(const float* __restrict__ Hm, const float* __restrict__ Wq,
                  const float* __restrict__ bq, int B, int Hd, int D) {
    __shared__ float As[8][128];
    __shared__ float Bs[8][128];
    const int tid = threadIdx.x;
    const int brow = blockIdx.y * 128, bcol = blockIdx.x * 128;
    const int tx = tid & 15, ty = tid >> 4;
    const int a_row = tid >> 1, a_k = (tid & 1) * 4;
    const int b_k = tid >> 5, b_c = (tid & 31) * 4;
    const float* Ap = Hm + (size_t)(brow + a_row) * Hd + a_k;
    const float* Bp = Wq + (size_t)b_k * D + bcol + b_c;
    float acc[8][8];
#pragma unroll
    for (int i = 0; i < 8; i++)
#pragma unroll
        for (int j = 0; j < 8; j++) acc[i][j] = 0.f;
    for (int k0 = 0; k0 < Hd; k0 += 8) {
        float4 av = *(const float4*)(Ap + k0);
        float4 bv = *(const float4*)(Bp + (size_t)k0 * D);
        __syncthreads();
        As[a_k + 0][a_row] = av.x; As[a_k + 1][a_row] = av.y;
        As[a_k + 2][a_row] = av.z; As[a_k + 3][a_row] = av.w;
        *(float4*)&Bs[b_k][b_c] = bv;
        __syncthreads();
#pragma unroll
        for (int kk = 0; kk < 8; kk++) {
            float ar[8], br[8];
            *(float4*)&ar[0] = *(const float4*)&As[kk][ty * 8];
            *(float4*)&ar[4] = *(const float4*)&As[kk][ty * 8 + 4];
            *(float4*)&br[0] = *(const float4*)&Bs[kk][tx * 8];
            *(float4*)&br[4] = *(const float4*)&Bs[kk][tx * 8 + 4];
#pragma unroll
            for (int i = 0; i < 8; i++)
#pragma unroll
                for (int j = 0; j < 8; j++) acc[i][j] += ar[i] * br[j];
        }
    }
#pragma unroll
    for (int i = 0; i < 8; i++) {
        int r = brow + ty * 8 + i;
#pragma unroll
        for (int j = 0; j < 8; j += 4) {
            int c = bcol + tx * 8 + j;
            float4 o;
            o.x = acc[i][j + 0] + bq[c + 0];
            o.y = acc[i][j + 1] + bq[c + 1];
            o.z = acc[i][j + 2] + bq[c + 2];
            o.w = acc[i][j + 3] + bq[c + 3];
            *(float4*)&g_q[(size_t)r * D + c] = o;
            __nv_bfloat162 p0 = __float22bfloat162_rn(make_float2(o.x, o.y));
            __nv_bfloat162 p1 = __float22bfloat162_rn(make_float2(o.z, o.w));
            uint2 pk; pk.x = *(uint32_t*)&p0; pk.y = *(uint32_t*)&p1;
            *(uint2*)&g_qb[(size_t)r * D + c] = pk;
        }
    }
}

// ---------------------------------------------------------------------------
// msq (exact fp32) + bf16 copy of mem
// ---------------------------------------------------------------------------
__global__ void msq_kernel(const float* __restrict__ Mem, int D) {
    const int r = blockIdx.x;
    const float4* p = (const float4*)(Mem + (size_t)r * D);
    float s = 0.f;
    for (int i = threadIdx.x; i < D / 4; i += 64) {
        float4 v = p[i];
        s += v.x * v.x + v.y * v.y + v.z * v.z + v.w * v.w;
        __nv_bfloat162 p0 = __float22bfloat162_rn(make_float2(v.x, v.y));
        __nv_bfloat162 p1 = __float22bfloat162_rn(make_float2(v.z, v.w));
        uint2 pk; pk.x = *(uint32_t*)&p0; pk.y = *(uint32_t*)&p1;
        *(uint2*)&g_mb[(size_t)r * D + i * 4] = pk;
    }
#pragma unroll
    for (int off = 16; off; off >>= 1) s += __shfl_down_sync(0xffffffffu, s, off);
    __shared__ float ws[2];
    if ((threadIdx.x & 31) == 0) ws[threadIdx.x >> 5] = s;
    __syncthreads();
    if (threadIdx.x == 0) g_msq[r] = ws[0] + ws[1];
}

// ---------------------------------------------------------------------------
// Kernel 3: dist = msq[m] - 2*(q.m) via WMMA bf16 with SMEM-staged tiles.
// CTA 128x128, 8 warps (2x4), warp 64x32. K=256 in 8 chunks of 32.
// Register-prefetch next chunk during compute. fp16 output.
// ---------------------------------------------------------------------------
#define ASTRIDE 40      // halves per smem row (80B, 16B-aligned rows)

__global__ __launch_bounds__(256, 2)
void dist_wmma_kernel(int B, int M, int D) {
    __shared__ __nv_bfloat16 As[128 * ASTRIDE];   // 10240 B
    __shared__ __nv_bfloat16 Bs[128 * ASTRIDE];   // 10240 B
    __shared__ float ebuf[8 * 256];               // 8 KB
    __shared__ float msq_s[128];
    const int tid = threadIdx.x;
    const int lane = tid & 31, wid = tid >> 5;
    const int warp_m = wid >> 2, warp_n = wid & 3;     // 2 x 4
    const int brow = blockIdx.y * 128;
    const int bcol = blockIdx.x * 128;

    if (tid < 128) msq_s[tid] = g_msq[bcol + tid];

    const __nv_bfloat16* Ag = g_qb + (size_t)brow * DN;
    const __nv_bfloat16* Bg = g_mb + (size_t)bcol * DN;

    const int r0 = tid >> 2, q0 = (tid & 3) * 8;
    const int r1 = r0 + 64, q1 = q0;

    uint4 ra0, ra1, rb0, rb1;
    ra0 = *(const uint4*)(Ag + (size_t)r0 * DN + q0);
    ra1 = *(const uint4*)(Ag + (size_t)r1 * DN + q1);
    rb0 = *(const uint4*)(Bg + (size_t)r0 * DN + q0);
    rb1 = *(const uint4*)(Bg + (size_t)r1 * DN + q1);

    wmma::fragment<wmma::accumulator, 16, 16, 16, float> acc[4][2];
#pragma unroll
    for (int mt = 0; mt < 4; mt++)
#pragma unroll
        for (int nt = 0; nt < 2; nt++) wmma::fill_fragment(acc[mt][nt], 0.f);

    for (int c = 0; c < 8; c++) {
        __syncthreads();
        *(uint4*)(As + r0 * ASTRIDE + q0) = ra0;
        *(uint4*)(As + r1 * ASTRIDE + q1) = ra1;
        *(uint4*)(Bs + r0 * ASTRIDE + q0) = rb0;
        *(uint4*)(Bs + r1 * ASTRIDE + q1) = rb1;
        if (c < 7) {
            int kb = (c + 1) * 32;
            ra0 = *(const uint4*)(Ag + (size_t)r0 * DN + kb + q0);
            ra1 = *(const uint4*)(Ag + (size_t)r1 * DN + kb + q1);
            rb0 = *(const uint4*)(Bg + (size_t)r0 * DN + kb + q0);
            rb1 = *(const uint4*)(Bg + (size_t)r1 * DN + kb + q1);
        }
        __syncthreads();

#pragma unroll
        for (int ks = 0; ks < 2; ks++) {
            wmma::fragment<wmma::matrix_b, 16, 16, 16, __nv_bfloat16, wmma::col_major> bf[2];
#pragma unroll
            for (int nt = 0; nt < 2; nt++)
                wmma::load_matrix_sync(bf[nt],
                    Bs + (warp_n * 32 + nt * 16) * ASTRIDE + ks * 16, ASTRIDE);
#pragma unroll
            for (int mt = 0; mt < 4; mt++) {
                wmma::fragment<wmma::matrix_a, 16, 16, 16, __nv_bfloat16, wmma::row_major> af;
                wmma::load_matrix_sync(af,
                    As + (warp_m * 64 + mt * 16) * ASTRIDE + ks * 16, ASTRIDE);
#pragma unroll
                for (int nt = 0; nt < 2; nt++)
                    wmma::mma_sync(acc[mt][nt], af, bf[nt], acc[mt][nt]);
            }
        }
    }

    float* eb = ebuf + wid * 256;
    const int er = lane >> 1, ec = (lane & 1) * 8;
#pragma unroll
    for (int mt = 0; mt < 4; mt++) {
#pragma unroll
        for (int nt = 0; nt < 2; nt++) {
            wmma::store_matrix_sync(eb, acc[mt][nt], 16, wmma::mem_row_major);
            __syncwarp();
            int grow = brow + warp_m * 64 + mt * 16 + er;
            int cl = warp_n * 32 + nt * 16 + ec;
            const float* e = eb + er * 16 + ec;
            __half2 h0 = __floats2half2_rn(msq_s[cl + 0] - 2.f * e[0],
                                           msq_s[cl + 1] - 2.f * e[1]);
            __half2 h1 = __floats2half2_rn(msq_s[cl + 2] - 2.f * e[2],
                                           msq_s[cl + 3] - 2.f * e[3]);
            __half2 h2 = __floats2half2_rn(msq_s[cl + 4] - 2.f * e[4],
                                           msq_s[cl + 5] - 2.f * e[5]);
            __half2 h3 = __floats2half2_rn(msq_s[cl + 6] - 2.f * e[6],
                                           msq_s[cl + 7] - 2.f * e[7]);
            uint4 pk;
            pk.x = *(uint32_t*)&h0; pk.y = *(uint32_t*)&h1;
            pk.z = *(uint32_t*)&h2; pk.w = *(uint32_t*)&h3;
            *(uint4*)&g_dist[(size_t)grow * M + bcol + cl] = pk;
            __syncwarp();
        }
    }
}

// ---------------------------------------------------------------------------
// Kernel 4: warp-per-row, dist rows streamed DIRECTLY from gmem (no smem row
// cache -> ~13KB smem -> high occupancy / memory-level parallelism).
// Sample stats -> threshold filter with both-sided retry -> top-32 via
// __reduce_min_sync -> exact fp32 rescore -> exact top-k -> softmax -> gather.
// ---------------------------------------------------------------------------
__global__ __launch_bounds__(128)
void topk_kernel(const float* __restrict__ Mem, const int* __restrict__ kp,
                 float* __restrict__ out, int M, int D) {
    __shared__ float sh_q[RPB * DN];         // 4 KB
    __shared__ uint32_t ckey[RPB][CAPB];     // 8 KB
    __shared__ int ccnt[RPB];
    __shared__ int scand[RPB][NCAND];
    __shared__ float cd[RPB][NCAND];
    __shared__ float swt[RPB][MAXK];
    __shared__ int ssel[RPB][MAXK];

    const int tid = threadIdx.x, lane = tid & 31, w = tid >> 5;
    const int b0 = blockIdx.x * RPB;
    int k = kp[0];
    if (k < 1) k = 1;
    if (k > MAXK) k = MAXK;

    // Phase A: q rows to smem (used by rescore)
    {
        const float4* qsrc = (const float4*)(g_q + (size_t)b0 * DN);
        float4* qdst = (float4*)sh_q;
        for (int i = tid; i < RPB * DN / 4; i += 128) qdst[i] = qsrc[i];
    }
    __syncthreads();

    const uint4* drow4 = (const uint4*)(g_dist + (size_t)(b0 + w) * MN);

    // Phase B: per-warp sample stats (256 elems, coalesced) -> thr = mu-2sg
    float s1 = 0.f, s2 = 0.f;
    {
        uint4 pk = drow4[lane];              // 32 lanes x 8 halves = 256 elems
        const __half2* hp = (const __half2*)&pk;
#pragma unroll
        for (int e = 0; e < 4; e++) {
            float2 f = __half22float2(hp[e]);
            s1 += f.x + f.y; s2 += f.x * f.x + f.y * f.y;
        }
    }
#pragma unroll
    for (int off = 16; off; off >>= 1) {
        s1 += __shfl_xor_sync(0xffffffffu, s1, off);
        s2 += __shfl_xor_sync(0xffffffffu, s2, off);
    }
    float mu = s1 * (1.f / 256.f);
    float sg = sqrtf(fmaxf(s2 * (1.f / 256.f) - mu * mu, 0.f));
    sg = fmaxf(sg, fabsf(mu) * 1e-4f + 1e-6f);
    float thr = mu - 2.f * sg;

    // Phase C: threshold filter straight from gmem (coalesced uint4).
    // Accept only NCAND<=cnt<=CAPB; else step +-0.5*sigma and retry.
    int cnt = 0;
    for (int attempt = 0; attempt < 10; attempt++) {
        __half thrh = __float2half_ru(thr);
        if (lane == 0) ccnt[w] = 0;
        __syncwarp();
#pragma unroll 4
        for (int j = 0; j < 16; j++) {
            int gi = j * 32 + lane;
            uint4 pk = drow4[gi];
            __half2 a = *(__half2*)&pk.x, b = *(__half2*)&pk.y;
            __half2 c2 = *(__half2*)&pk.z, d2 = *(__half2*)&pk.w;
            __half2 m2 = __hmin2(__hmin2(a, b), __hmin2(c2, d2));
            __half mn = __hmin(__low2half(m2), __high2half(m2));
            if (__hlt(mn, thrh)) {
                const __half* hp = (const __half*)&pk;
                int base = gi * 8;
#pragma unroll
                for (int e = 0; e < 8; e++) {
                    __half h = hp[e];
                    if (__hlt(h, thrh)) {
                        unsigned short ub = __half_as_ushort(h);
                        uint32_t o = (ub & 0x8000u) ? (uint32_t)((~ub) & 0xFFFFu)
                                                    : (uint32_t)(ub | 0x8000u);
                        uint32_t key = (o << 12) | (uint32_t)(base + e);
                        int pos = atomicAdd(&ccnt[w], 1);
                        if (pos < CAPB) ckey[w][pos] = key;
                    }
                }
            }
        }
        __syncwarp();
        cnt = ccnt[w];
        if (cnt >= NCAND && cnt <= CAPB) break;
        thr += (cnt < NCAND) ? 0.5f * sg : -0.5f * sg;
        __syncwarp();
    }
    if (cnt > CAPB) cnt = CAPB;

    // Phase D: top-32 keys via warp redux (keys unique -> deterministic)
    {
        uint32_t lv[CAPB / 32];
#pragma unroll
        for (int j = 0; j < CAPB / 32; j++) {
            int s = lane + 32 * j;
            lv[j] = (s < cnt) ? ckey[w][s] : 0xFFFFFFFFu;
        }
        uint32_t lmin = 0xFFFFFFFFu;
#pragma unroll
        for (int j = 0; j < CAPB / 32; j++) lmin = min(lmin, lv[j]);
        for (int it = 0; it < NCAND; it++) {
            uint32_t g = __reduce_min_sync(0xffffffffu, lmin);
            if (lane == 0) scand[w][it] = (int)(g & 0xFFFu);
            unsigned bal = __ballot_sync(0xffffffffu, lmin == g);
            int wl = __ffs((int)bal) - 1;
            if (lane == wl) {
#pragma unroll
                for (int j = 0; j < CAPB / 32; j++)
                    if (lv[j] == g) lv[j] = 0xFFFFFFFFu;
                lmin = 0xFFFFFFFFu;
#pragma unroll
                for (int j = 0; j < CAPB / 32; j++) lmin = min(lmin, lv[j]);
            }
        }
    }
    __syncwarp();

    // Phase E: exact rescore — one candidate per thread (serial 256-dot)
    {
        int midx = scand[w][lane];
        const float4* mp = (const float4*)(Mem + (size_t)midx * DN);
        const float4* qp = (const float4*)(sh_q + w * DN);
        float dot = 0.f;
#pragma unroll 8
        for (int i = 0; i < 64; i++) {
            float4 a = qp[i], bb = mp[i];
            dot += a.x * bb.x + a.y * bb.y + a.z * bb.z + a.w * bb.w;
        }
        cd[w][lane] = g_msq[midx] - 2.f * dot;
    }
    __syncwarp();

    // Phase F: exact top-k among 32, softmax(-dist), weighted gather
    {
        float v = cd[w][lane];
        for (int it = 0; it < k; it++) {
            float m = v; int s = lane;
#pragma unroll
            for (int off = 16; off; off >>= 1) {
                float m2 = __shfl_xor_sync(0xffffffffu, m, off);
                int s2 = __shfl_xor_sync(0xffffffffu, s, off);
                if (m2 < m || (m2 == m && s2 < s)) { m = m2; s = s2; }
            }
            if (lane == 0) { swt[w][it] = m; ssel[w][it] = scand[w][s]; }
            if (lane == s) v = BIGF;
        }
        __syncwarp();
        if (lane == 0) {
            float d0 = swt[w][0], ssum = 0.f;
            for (int i = 0; i < k; i++) {
                float e = expf(d0 - swt[w][i]);
                swt[w][i] = e; ssum += e;
            }
            float inv = 1.f / ssum;
            for (int i = 0; i < k; i++) swt[w][i] *= inv;
        }
        __syncwarp();

        const int d0 = lane * 8;
        float acc[8];
#pragma unroll
        for (int e = 0; e < 8; e++) acc[e] = 0.f;
        for (int i = 0; i < k; i++) {
            float wt = swt[w][i];
            const float4* mp = (const float4*)(Mem + (size_t)ssel[w][i] * DN + d0);
            float4 a = mp[0], bb = mp[1];
            acc[0] += wt * a.x;  acc[1] += wt * a.y;
            acc[2] += wt * a.z;  acc[3] += wt * a.w;
            acc[4] += wt * bb.x; acc[5] += wt * bb.y;
            acc[6] += wt * bb.z; acc[7] += wt * bb.w;
        }
        float4 o0 = make_float4(acc[0], acc[1], acc[2], acc[3]);
        float4 o1 = make_float4(acc[4], acc[5], acc[6], acc[7]);
        *(float4*)&out[(size_t)(b0 + w) * DN + d0] = o0;
        *(float4*)&out[(size_t)(b0 + w) * DN + d0 + 4] = o1;
    }
}

// ---------------------------------------------------------------------------
extern "C" void kernel_launch(void* const* d_in, const int* in_sizes, int n_in,
                              void* d_out, int out_size) {
    const float* h   = (const float*)d_in[0];
    const float* mem = (const float*)d_in[1];
    const float* Wq  = (const float*)d_in[2];
    const float* bq  = (const float*)d_in[3];
    const int*   kp  = (const int*)d_in[4];
    float* out = (float*)d_out;

    const int D  = in_sizes[3];
    const int Hd = in_sizes[2] / D;
    const int B  = in_sizes[0] / Hd;
    const int M  = in_sizes[1] / D;

    dim3 g1(D / 128, B / 128);
    qproj_kernel<<<g1, 256>>>(h, Wq, bq, B, Hd, D);
    msq_kernel<<<M, 64>>>(mem, D);
    dim3 g3(M / 128, B / 128);
    dist_wmma_kernel<<<g3, 256>>>(B, M, D);
    topk_kernel<<<B / RPB, 128>>>(mem, kp, out, M, D);
}

// round 13
// speedup vs baseline: 7.9097x; 1.0998x over previous
#include <cuda_runtime.h>
#include <cuda_bf16.h>
#include <cuda_fp16.h>
#include <mma.h>
#include <cstdint>
#include <math.h>

using namespace nvcuda;

// Problem shape: B=8192, H=512, M=4096, D=256, k<=32
#define BN 8192
#define MN 4096
#define DN 256
#define MAXK 32
#define NCAND 32
#define RPB 4           // rows per topk block
#define CAPB 512        // candidate slots per row
#define BIGF 3.0e37f

__device__ float g_q[BN * DN];               // exact fp32 q (for rescore)
__device__ __nv_bfloat16 g_qb[BN * DN];      // bf16 q (for WMMA)
__device__ __nv_bfloat16 g_mb[MN * DN];      // bf16 mem (for WMMA)
__device__ float g_msq[MN];                  // exact ||m||^2
__device__ __half g_dist[(size_t)BN * MN];   // 67MB approx dists (selection only)

// ---------------------------------------------------------------------------
// Kernel 1: q = h @ Wq + bq  (exact fp32 SGEMM) + bf16 copy of q
// ---------------------------------------------------------------------------
__global__ __launch_bounds__(256, 2)
void qproj_kernel(const float* __restrict__ Hm, const float* __restrict__ Wq,
                  const float* __restrict__ bq, int B, int Hd, int D) {
    __shared__ float As[8][128];
    __shared__ float Bs[8][128];
    const int tid = threadIdx.x;
    const int brow = blockIdx.y * 128, bcol = blockIdx.x * 128;
    const int tx = tid & 15, ty = tid >> 4;
    const int a_row = tid >> 1, a_k = (tid & 1) * 4;
    const int b_k = tid >> 5, b_c = (tid & 31) * 4;
    const float* Ap = Hm + (size_t)(brow + a_row) * Hd + a_k;
    const float* Bp = Wq + (size_t)b_k * D + bcol + b_c;
    float acc[8][8];
#pragma unroll
    for (int i = 0; i < 8; i++)
#pragma unroll
        for (int j = 0; j < 8; j++) acc[i][j] = 0.f;
    for (int k0 = 0; k0 < Hd; k0 += 8) {
        float4 av = *(const float4*)(Ap + k0);
        float4 bv = *(const float4*)(Bp + (size_t)k0 * D);
        __syncthreads();
        As[a_k + 0][a_row] = av.x; As[a_k + 1][a_row] = av.y;
        As[a_k + 2][a_row] = av.z; As[a_k + 3][a_row] = av.w;
        *(float4*)&Bs[b_k][b_c] = bv;
        __syncthreads();
#pragma unroll
        for (int kk = 0; kk < 8; kk++) {
            float ar[8], br[8];
            *(float4*)&ar[0] = *(const float4*)&As[kk][ty * 8];
            *(float4*)&ar[4] = *(const float4*)&As[kk][ty * 8 + 4];
            *(float4*)&br[0] = *(const float4*)&Bs[kk][tx * 8];
            *(float4*)&br[4] = *(const float4*)&Bs[kk][tx * 8 + 4];
#pragma unroll
            for (int i = 0; i < 8; i++)
#pragma unroll
                for (int j = 0; j < 8; j++) acc[i][j] += ar[i] * br[j];
        }
    }
#pragma unroll
    for (int i = 0; i < 8; i++) {
        int r = brow + ty * 8 + i;
#pragma unroll
        for (int j = 0; j < 8; j += 4) {
            int c = bcol + tx * 8 + j;
            float4 o;
            o.x = acc[i][j + 0] + bq[c + 0];
            o.y = acc[i][j + 1] + bq[c + 1];
            o.z = acc[i][j + 2] + bq[c + 2];
            o.w = acc[i][j + 3] + bq[c + 3];
            *(float4*)&g_q[(size_t)r * D + c] = o;
            __nv_bfloat162 p0 = __float22bfloat162_rn(make_float2(o.x, o.y));
            __nv_bfloat162 p1 = __float22bfloat162_rn(make_float2(o.z, o.w));
            uint2 pk; pk.x = *(uint32_t*)&p0; pk.y = *(uint32_t*)&p1;
            *(uint2*)&g_qb[(size_t)r * D + c] = pk;
        }
    }
}

// ---------------------------------------------------------------------------
// msq (exact fp32) + bf16 copy of mem
// ---------------------------------------------------------------------------
__global__ void msq_kernel(const float* __restrict__ Mem, int D) {
    const int r = blockIdx.x;
    const float4* p = (const float4*)(Mem + (size_t)r * D);
    float s = 0.f;
    for (int i = threadIdx.x; i < D / 4; i += 64) {
        float4 v = p[i];
        s += v.x * v.x + v.y * v.y + v.z * v.z + v.w * v.w;
        __nv_bfloat162 p0 = __float22bfloat162_rn(make_float2(v.x, v.y));
        __nv_bfloat162 p1 = __float22bfloat162_rn(make_float2(v.z, v.w));
        uint2 pk; pk.x = *(uint32_t*)&p0; pk.y = *(uint32_t*)&p1;
        *(uint2*)&g_mb[(size_t)r * D + i * 4] = pk;
    }
#pragma unroll
    for (int off = 16; off; off >>= 1) s += __shfl_down_sync(0xffffffffu, s, off);
    __shared__ float ws[2];
    if ((threadIdx.x & 31) == 0) ws[threadIdx.x >> 5] = s;
    __syncthreads();
    if (threadIdx.x == 0) g_msq[r] = ws[0] + ws[1];
}

// ---------------------------------------------------------------------------
// Kernel 3: dist = msq[m] - 2*(q.m) via WMMA bf16 with SMEM-staged tiles.
// CTA 128x128, 8 warps (2x4), warp 64x32. K=256 in 8 chunks of 32.
// Register-prefetch next chunk during compute. fp16 output.
// ---------------------------------------------------------------------------
#define ASTRIDE 40      // halves per smem row (80B, 16B-aligned rows)

__global__ __launch_bounds__(256, 2)
void dist_wmma_kernel(int B, int M, int D) {
    __shared__ __nv_bfloat16 As[128 * ASTRIDE];   // 10240 B
    __shared__ __nv_bfloat16 Bs[128 * ASTRIDE];   // 10240 B
    __shared__ float ebuf[8 * 256];               // 8 KB
    __shared__ float msq_s[128];
    const int tid = threadIdx.x;
    const int lane = tid & 31, wid = tid >> 5;
    const int warp_m = wid >> 2, warp_n = wid & 3;     // 2 x 4
    const int brow = blockIdx.y * 128;
    const int bcol = blockIdx.x * 128;

    if (tid < 128) msq_s[tid] = g_msq[bcol + tid];

    const __nv_bfloat16* Ag = g_qb + (size_t)brow * DN;
    const __nv_bfloat16* Bg = g_mb + (size_t)bcol * DN;

    const int r0 = tid >> 2, q0 = (tid & 3) * 8;
    const int r1 = r0 + 64, q1 = q0;

    uint4 ra0, ra1, rb0, rb1;
    ra0 = *(const uint4*)(Ag + (size_t)r0 * DN + q0);
    ra1 = *(const uint4*)(Ag + (size_t)r1 * DN + q1);
    rb0 = *(const uint4*)(Bg + (size_t)r0 * DN + q0);
    rb1 = *(const uint4*)(Bg + (size_t)r1 * DN + q1);

    wmma::fragment<wmma::accumulator, 16, 16, 16, float> acc[4][2];
#pragma unroll
    for (int mt = 0; mt < 4; mt++)
#pragma unroll
        for (int nt = 0; nt < 2; nt++) wmma::fill_fragment(acc[mt][nt], 0.f);

    for (int c = 0; c < 8; c++) {
        __syncthreads();
        *(uint4*)(As + r0 * ASTRIDE + q0) = ra0;
        *(uint4*)(As + r1 * ASTRIDE + q1) = ra1;
        *(uint4*)(Bs + r0 * ASTRIDE + q0) = rb0;
        *(uint4*)(Bs + r1 * ASTRIDE + q1) = rb1;
        if (c < 7) {
            int kb = (c + 1) * 32;
            ra0 = *(const uint4*)(Ag + (size_t)r0 * DN + kb + q0);
            ra1 = *(const uint4*)(Ag + (size_t)r1 * DN + kb + q1);
            rb0 = *(const uint4*)(Bg + (size_t)r0 * DN + kb + q0);
            rb1 = *(const uint4*)(Bg + (size_t)r1 * DN + kb + q1);
        }
        __syncthreads();

#pragma unroll
        for (int ks = 0; ks < 2; ks++) {
            wmma::fragment<wmma::matrix_b, 16, 16, 16, __nv_bfloat16, wmma::col_major> bf[2];
#pragma unroll
            for (int nt = 0; nt < 2; nt++)
                wmma::load_matrix_sync(bf[nt],
                    Bs + (warp_n * 32 + nt * 16) * ASTRIDE + ks * 16, ASTRIDE);
#pragma unroll
            for (int mt = 0; mt < 4; mt++) {
                wmma::fragment<wmma::matrix_a, 16, 16, 16, __nv_bfloat16, wmma::row_major> af;
                wmma::load_matrix_sync(af,
                    As + (warp_m * 64 + mt * 16) * ASTRIDE + ks * 16, ASTRIDE);
#pragma unroll
                for (int nt = 0; nt < 2; nt++)
                    wmma::mma_sync(acc[mt][nt], af, bf[nt], acc[mt][nt]);
            }
        }
    }

    float* eb = ebuf + wid * 256;
    const int er = lane >> 1, ec = (lane & 1) * 8;
#pragma unroll
    for (int mt = 0; mt < 4; mt++) {
#pragma unroll
        for (int nt = 0; nt < 2; nt++) {
            wmma::store_matrix_sync(eb, acc[mt][nt], 16, wmma::mem_row_major);
            __syncwarp();
            int grow = brow + warp_m * 64 + mt * 16 + er;
            int cl = warp_n * 32 + nt * 16 + ec;
            const float* e = eb + er * 16 + ec;
            __half2 h0 = __floats2half2_rn(msq_s[cl + 0] - 2.f * e[0],
                                           msq_s[cl + 1] - 2.f * e[1]);
            __half2 h1 = __floats2half2_rn(msq_s[cl + 2] - 2.f * e[2],
                                           msq_s[cl + 3] - 2.f * e[3]);
            __half2 h2 = __floats2half2_rn(msq_s[cl + 4] - 2.f * e[4],
                                           msq_s[cl + 5] - 2.f * e[5]);
            __half2 h3 = __floats2half2_rn(msq_s[cl + 6] - 2.f * e[6],
                                           msq_s[cl + 7] - 2.f * e[7]);
            uint4 pk;
            pk.x = *(uint32_t*)&h0; pk.y = *(uint32_t*)&h1;
            pk.z = *(uint32_t*)&h2; pk.w = *(uint32_t*)&h3;
            *(uint4*)&g_dist[(size_t)grow * M + bcol + cl] = pk;
            __syncwarp();
        }
    }
}

// ---------------------------------------------------------------------------
// Kernel 4: warp-per-row, dist rows streamed directly from gmem.
// Sample stats -> threshold filter (both-sided retry) -> top-32 via
// __reduce_min_sync -> COALESCED warp-cooperative exact fp32 rescore ->
// exact top-k -> softmax -> gather. 4 rows per 128-thread block.
// ---------------------------------------------------------------------------
__global__ __launch_bounds__(128)
void topk_kernel(const float* __restrict__ Mem, const int* __restrict__ kp,
                 float* __restrict__ out, int M, int D) {
    __shared__ float sh_q[RPB * DN];         // 4 KB
    __shared__ uint32_t ckey[RPB][CAPB];     // 8 KB
    __shared__ int ccnt[RPB];
    __shared__ int scand[RPB][NCAND];
    __shared__ float cd[RPB][NCAND];
    __shared__ float swt[RPB][MAXK];
    __shared__ int ssel[RPB][MAXK];

    const int tid = threadIdx.x, lane = tid & 31, w = tid >> 5;
    const int b0 = blockIdx.x * RPB;
    int k = kp[0];
    if (k < 1) k = 1;
    if (k > MAXK) k = MAXK;

    // Phase A: q rows to smem (used by rescore)
    {
        const float4* qsrc = (const float4*)(g_q + (size_t)b0 * DN);
        float4* qdst = (float4*)sh_q;
        for (int i = tid; i < RPB * DN / 4; i += 128) qdst[i] = qsrc[i];
    }
    __syncthreads();

    const uint4* drow4 = (const uint4*)(g_dist + (size_t)(b0 + w) * MN);

    // Phase B: per-warp sample stats (256 elems, coalesced) -> thr = mu-2sg
    float s1 = 0.f, s2 = 0.f;
    {
        uint4 pk = drow4[lane];              // 32 lanes x 8 halves = 256 elems
        const __half2* hp = (const __half2*)&pk;
#pragma unroll
        for (int e = 0; e < 4; e++) {
            float2 f = __half22float2(hp[e]);
            s1 += f.x + f.y; s2 += f.x * f.x + f.y * f.y;
        }
    }
#pragma unroll
    for (int off = 16; off; off >>= 1) {
        s1 += __shfl_xor_sync(0xffffffffu, s1, off);
        s2 += __shfl_xor_sync(0xffffffffu, s2, off);
    }
    float mu = s1 * (1.f / 256.f);
    float sg = sqrtf(fmaxf(s2 * (1.f / 256.f) - mu * mu, 0.f));
    sg = fmaxf(sg, fabsf(mu) * 1e-4f + 1e-6f);
    float thr = mu - 2.f * sg;

    // Phase C: threshold filter straight from gmem (coalesced uint4).
    // Accept only NCAND<=cnt<=CAPB; else step +-0.5*sigma and retry.
    int cnt = 0;
    for (int attempt = 0; attempt < 10; attempt++) {
        __half thrh = __float2half_ru(thr);
        if (lane == 0) ccnt[w] = 0;
        __syncwarp();
#pragma unroll 4
        for (int j = 0; j < 16; j++) {
            int gi = j * 32 + lane;
            uint4 pk = drow4[gi];
            __half2 a = *(__half2*)&pk.x, b = *(__half2*)&pk.y;
            __half2 c2 = *(__half2*)&pk.z, d2 = *(__half2*)&pk.w;
            __half2 m2 = __hmin2(__hmin2(a, b), __hmin2(c2, d2));
            __half mn = __hmin(__low2half(m2), __high2half(m2));
            if (__hlt(mn, thrh)) {
                const __half* hp = (const __half*)&pk;
                int base = gi * 8;
#pragma unroll
                for (int e = 0; e < 8; e++) {
                    __half h = hp[e];
                    if (__hlt(h, thrh)) {
                        unsigned short ub = __half_as_ushort(h);
                        uint32_t o = (ub & 0x8000u) ? (uint32_t)((~ub) & 0xFFFFu)
                                                    : (uint32_t)(ub | 0x8000u);
                        uint32_t key = (o << 12) | (uint32_t)(base + e);
                        int pos = atomicAdd(&ccnt[w], 1);
                        if (pos < CAPB) ckey[w][pos] = key;
                    }
                }
            }
        }
        __syncwarp();
        cnt = ccnt[w];
        if (cnt >= NCAND && cnt <= CAPB) break;
        thr += (cnt < NCAND) ? 0.5f * sg : -0.5f * sg;
        __syncwarp();
    }
    if (cnt > CAPB) cnt = CAPB;

    // Phase D: top-32 keys via warp redux (keys unique -> deterministic)
    {
        uint32_t lv[CAPB / 32];
#pragma unroll
        for (int j = 0; j < CAPB / 32; j++) {
            int s = lane + 32 * j;
            lv[j] = (s < cnt) ? ckey[w][s] : 0xFFFFFFFFu;
        }
        uint32_t lmin = 0xFFFFFFFFu;
#pragma unroll
        for (int j = 0; j < CAPB / 32; j++) lmin = min(lmin, lv[j]);
        for (int it = 0; it < NCAND; it++) {
            uint32_t g = __reduce_min_sync(0xffffffffu, lmin);
            if (lane == 0) scand[w][it] = (int)(g & 0xFFFu);
            unsigned bal = __ballot_sync(0xffffffffu, lmin == g);
            int wl = __ffs((int)bal) - 1;
            if (lane == wl) {
#pragma unroll
                for (int j = 0; j < CAPB / 32; j++)
                    if (lv[j] == g) lv[j] = 0xFFFFFFFFu;
                lmin = 0xFFFFFFFFu;
#pragma unroll
                for (int j = 0; j < CAPB / 32; j++) lmin = min(lmin, lv[j]);
            }
        }
    }
    __syncwarp();

    // Phase E: exact rescore — warp-cooperative, COALESCED. One candidate at
    // a time: 32 lanes cover the full 1KB row (2x ld.128 each), butterfly
    // reduce (deterministic, lane-uniform).
    {
        const float4* qp = (const float4*)(sh_q + w * DN);
        const float4 qa = qp[lane * 2], qb2 = qp[lane * 2 + 1];
#pragma unroll 4
        for (int ci = 0; ci < NCAND; ci++) {
            int midx = scand[w][ci];
            const float4* mp = (const float4*)(Mem + (size_t)midx * DN);
            float4 ma = mp[lane * 2], mb2 = mp[lane * 2 + 1];
            float dot = qa.x * ma.x + qa.y * ma.y + qa.z * ma.z + qa.w * ma.w
                      + qb2.x * mb2.x + qb2.y * mb2.y + qb2.z * mb2.z + qb2.w * mb2.w;
#pragma unroll
            for (int off = 16; off; off >>= 1)
                dot += __shfl_xor_sync(0xffffffffu, dot, off);
            if (lane == 0) cd[w][ci] = g_msq[midx] - 2.f * dot;
        }
    }
    __syncwarp();

    // Phase F: exact top-k among 32, softmax(-dist), weighted gather
    {
        float v = cd[w][lane];
        for (int it = 0; it < k; it++) {
            float m = v; int s = lane;
#pragma unroll
            for (int off = 16; off; off >>= 1) {
                float m2 = __shfl_xor_sync(0xffffffffu, m, off);
                int s2 = __shfl_xor_sync(0xffffffffu, s, off);
                if (m2 < m || (m2 == m && s2 < s)) { m = m2; s = s2; }
            }
            if (lane == 0) { swt[w][it] = m; ssel[w][it] = scand[w][s]; }
            if (lane == s) v = BIGF;
        }
        __syncwarp();
        if (lane == 0) {
            float d0 = swt[w][0], ssum = 0.f;
            for (int i = 0; i < k; i++) {
                float e = expf(d0 - swt[w][i]);
                swt[w][i] = e; ssum += e;
            }
            float inv = 1.f / ssum;
            for (int i = 0; i < k; i++) swt[w][i] *= inv;
        }
        __syncwarp();

        const int d0 = lane * 8;
        float acc[8];
#pragma unroll
        for (int e = 0; e < 8; e++) acc[e] = 0.f;
        for (int i = 0; i < k; i++) {
            float wt = swt[w][i];
            const float4* mp = (const float4*)(Mem + (size_t)ssel[w][i] * DN + d0);
            float4 a = mp[0], bb = mp[1];
            acc[0] += wt * a.x;  acc[1] += wt * a.y;
            acc[2] += wt * a.z;  acc[3] += wt * a.w;
            acc[4] += wt * bb.x; acc[5] += wt * bb.y;
            acc[6] += wt * bb.z; acc[7] += wt * bb.w;
        }
        float4 o0 = make_float4(acc[0], acc[1], acc[2], acc[3]);
        float4 o1 = make_float4(acc[4], acc[5], acc[6], acc[7]);
        *(float4*)&out[(size_t)(b0 + w) * DN + d0] = o0;
        *(float4*)&out[(size_t)(b0 + w) * DN + d0 + 4] = o1;
    }
}

// ---------------------------------------------------------------------------
extern "C" void kernel_launch(void* const* d_in, const int* in_sizes, int n_in,
                              void* d_out, int out_size) {
    const float* h   = (const float*)d_in[0];
    const float* mem = (const float*)d_in[1];
    const float* Wq  = (const float*)d_in[2];
    const float* bq  = (const float*)d_in[3];
    const int*   kp  = (const int*)d_in[4];
    float* out = (float*)d_out;

    const int D  = in_sizes[3];
    const int Hd = in_sizes[2] / D;
    const int B  = in_sizes[0] / Hd;
    const int M  = in_sizes[1] / D;

    dim3 g1(D / 128, B / 128);
    qproj_kernel<<<g1, 256>>>(h, Wq, bq, B, Hd, D);
    msq_kernel<<<M, 64>>>(mem, D);
    dim3 g3(M / 128, B / 128);
    dist_wmma_kernel<<<g3, 256>>>(B, M, D);
    topk_kernel<<<B / RPB, 128>>>(mem, kp, out, M, D);
}

// round 14
// speedup vs baseline: 8.3091x; 1.0505x over previous
#include <cuda_runtime.h>
#include <cuda_bf16.h>
#include <cuda_fp16.h>
#include <mma.h>
#include <cstdint>
#include <math.h>

using namespace nvcuda;

// Problem shape: B=8192, H=512, M=4096, D=256, k<=32
#define BN 8192
#define MN 4096
#define DN 256
#define MAXK 32
#define NCAND 32
#define RPB 4           // rows per topk block
#define CAPB 512        // candidate slots per row
#define BIGF 3.0e37f

__device__ float g_q[BN * DN];               // exact fp32 q (for rescore)
__device__ __nv_bfloat16 g_qb[BN * DN];      // bf16 q (for WMMA)
__device__ __nv_bfloat16 g_mb[MN * DN];      // bf16 mem (for WMMA)
__device__ float g_msq[MN];                  // exact ||m||^2
__device__ __half g_dist[(size_t)BN * MN];   // 67MB approx dists (selection only)

// ---------------------------------------------------------------------------
// Kernel 1: q = h @ Wq + bq  (exact fp32 SGEMM) + bf16 copy of q
// ---------------------------------------------------------------------------
__global__ __launch_bounds__(256, 2)
void qproj_kernel(const float* __restrict__ Hm, const float* __restrict__ Wq,
                  const float* __restrict__ bq, int B, int Hd, int D) {
    __shared__ float As[8][128];
    __shared__ float Bs[8][128];
    const int tid = threadIdx.x;
    const int brow = blockIdx.y * 128, bcol = blockIdx.x * 128;
    const int tx = tid & 15, ty = tid >> 4;
    const int a_row = tid >> 1, a_k = (tid & 1) * 4;
    const int b_k = tid >> 5, b_c = (tid & 31) * 4;
    const float* Ap = Hm + (size_t)(brow + a_row) * Hd + a_k;
    const float* Bp = Wq + (size_t)b_k * D + bcol + b_c;
    float acc[8][8];
#pragma unroll
    for (int i = 0; i < 8; i++)
#pragma unroll
        for (int j = 0; j < 8; j++) acc[i][j] = 0.f;
    for (int k0 = 0; k0 < Hd; k0 += 8) {
        float4 av = *(const float4*)(Ap + k0);
        float4 bv = *(const float4*)(Bp + (size_t)k0 * D);
        __syncthreads();
        As[a_k + 0][a_row] = av.x; As[a_k + 1][a_row] = av.y;
        As[a_k + 2][a_row] = av.z; As[a_k + 3][a_row] = av.w;
        *(float4*)&Bs[b_k][b_c] = bv;
        __syncthreads();
#pragma unroll
        for (int kk = 0; kk < 8; kk++) {
            float ar[8], br[8];
            *(float4*)&ar[0] = *(const float4*)&As[kk][ty * 8];
            *(float4*)&ar[4] = *(const float4*)&As[kk][ty * 8 + 4];
            *(float4*)&br[0] = *(const float4*)&Bs[kk][tx * 8];
            *(float4*)&br[4] = *(const float4*)&Bs[kk][tx * 8 + 4];
#pragma unroll
            for (int i = 0; i < 8; i++)
#pragma unroll
                for (int j = 0; j < 8; j++) acc[i][j] += ar[i] * br[j];
        }
    }
#pragma unroll
    for (int i = 0; i < 8; i++) {
        int r = brow + ty * 8 + i;
#pragma unroll
        for (int j = 0; j < 8; j += 4) {
            int c = bcol + tx * 8 + j;
            float4 o;
            o.x = acc[i][j + 0] + bq[c + 0];
            o.y = acc[i][j + 1] + bq[c + 1];
            o.z = acc[i][j + 2] + bq[c + 2];
            o.w = acc[i][j + 3] + bq[c + 3];
            *(float4*)&g_q[(size_t)r * D + c] = o;
            __nv_bfloat162 p0 = __float22bfloat162_rn(make_float2(o.x, o.y));
            __nv_bfloat162 p1 = __float22bfloat162_rn(make_float2(o.z, o.w));
            uint2 pk; pk.x = *(uint32_t*)&p0; pk.y = *(uint32_t*)&p1;
            *(uint2*)&g_qb[(size_t)r * D + c] = pk;
        }
    }
}

// ---------------------------------------------------------------------------
// msq (exact fp32) + bf16 copy of mem
// ---------------------------------------------------------------------------
__global__ void msq_kernel(const float* __restrict__ Mem, int D) {
    const int r = blockIdx.x;
    const float4* p = (const float4*)(Mem + (size_t)r * D);
    float s = 0.f;
    for (int i = threadIdx.x; i < D / 4; i += 64) {
        float4 v = p[i];
        s += v.x * v.x + v.y * v.y + v.z * v.z + v.w * v.w;
        __nv_bfloat162 p0 = __float22bfloat162_rn(make_float2(v.x, v.y));
        __nv_bfloat162 p1 = __float22bfloat162_rn(make_float2(v.z, v.w));
        uint2 pk; pk.x = *(uint32_t*)&p0; pk.y = *(uint32_t*)&p1;
        *(uint2*)&g_mb[(size_t)r * D + i * 4] = pk;
    }
#pragma unroll
    for (int off = 16; off; off >>= 1) s += __shfl_down_sync(0xffffffffu, s, off);
    __shared__ float ws[2];
    if ((threadIdx.x & 31) == 0) ws[threadIdx.x >> 5] = s;
    __syncthreads();
    if (threadIdx.x == 0) g_msq[r] = ws[0] + ws[1];
}

// ---------------------------------------------------------------------------
// Kernel 3: dist = msq[m] - 2*(q.m) via WMMA bf16, DOUBLE-BUFFERED smem.
// CTA 128x128, 8 warps (2x4), warp 64x32. K=256 in 8 chunks of 32.
// One __syncthreads per chunk; epilogue staging aliases the stage memory.
// ---------------------------------------------------------------------------
#define ASTRIDE 40                  // halves per smem row (80B)
#define STAGE_BYTES 20480           // As 10240 + Bs 10240

__global__ __launch_bounds__(256, 2)
void dist_wmma_kernel(int B, int M, int D) {
    __shared__ __align__(16) char sbuf[2 * STAGE_BYTES];   // 40 KB
    __shared__ float msq_s[128];
    const int tid = threadIdx.x;
    const int lane = tid & 31, wid = tid >> 5;
    const int warp_m = wid >> 2, warp_n = wid & 3;     // 2 x 4
    const int brow = blockIdx.y * 128;
    const int bcol = blockIdx.x * 128;

    if (tid < 128) msq_s[tid] = g_msq[bcol + tid];

    const __nv_bfloat16* Ag = g_qb + (size_t)brow * DN;
    const __nv_bfloat16* Bg = g_mb + (size_t)bcol * DN;

    const int r0 = tid >> 2, q0 = (tid & 3) * 8;
    const int r1 = r0 + 64, q1 = q0;

    uint4 ra0, ra1, rb0, rb1;
    ra0 = *(const uint4*)(Ag + (size_t)r0 * DN + q0);
    ra1 = *(const uint4*)(Ag + (size_t)r1 * DN + q1);
    rb0 = *(const uint4*)(Bg + (size_t)r0 * DN + q0);
    rb1 = *(const uint4*)(Bg + (size_t)r1 * DN + q1);

    wmma::fragment<wmma::accumulator, 16, 16, 16, float> acc[4][2];
#pragma unroll
    for (int mt = 0; mt < 4; mt++)
#pragma unroll
        for (int nt = 0; nt < 2; nt++) wmma::fill_fragment(acc[mt][nt], 0.f);

    // store chunk 0 into stage 0
    {
        __nv_bfloat16* As0 = (__nv_bfloat16*)sbuf;
        __nv_bfloat16* Bs0 = (__nv_bfloat16*)(sbuf + 10240);
        *(uint4*)(As0 + r0 * ASTRIDE + q0) = ra0;
        *(uint4*)(As0 + r1 * ASTRIDE + q1) = ra1;
        *(uint4*)(Bs0 + r0 * ASTRIDE + q0) = rb0;
        *(uint4*)(Bs0 + r1 * ASTRIDE + q1) = rb1;
    }
    __syncthreads();

    for (int c = 0; c < 8; c++) {
        const int st = c & 1;
        const __nv_bfloat16* As = (const __nv_bfloat16*)(sbuf + st * STAGE_BYTES);
        const __nv_bfloat16* Bs = As + 10240 / 2;

        // issue next chunk's gmem loads early (overlap with MMA below)
        if (c < 7) {
            int kb = (c + 1) * 32;
            ra0 = *(const uint4*)(Ag + (size_t)r0 * DN + kb + q0);
            ra1 = *(const uint4*)(Ag + (size_t)r1 * DN + kb + q1);
            rb0 = *(const uint4*)(Bg + (size_t)r0 * DN + kb + q0);
            rb1 = *(const uint4*)(Bg + (size_t)r1 * DN + kb + q1);
        }

#pragma unroll
        for (int ks = 0; ks < 2; ks++) {
            wmma::fragment<wmma::matrix_b, 16, 16, 16, __nv_bfloat16, wmma::col_major> bf[2];
#pragma unroll
            for (int nt = 0; nt < 2; nt++)
                wmma::load_matrix_sync(bf[nt],
                    Bs + (warp_n * 32 + nt * 16) * ASTRIDE + ks * 16, ASTRIDE);
#pragma unroll
            for (int mt = 0; mt < 4; mt++) {
                wmma::fragment<wmma::matrix_a, 16, 16, 16, __nv_bfloat16, wmma::row_major> af;
                wmma::load_matrix_sync(af,
                    As + (warp_m * 64 + mt * 16) * ASTRIDE + ks * 16, ASTRIDE);
#pragma unroll
                for (int nt = 0; nt < 2; nt++)
                    wmma::mma_sync(acc[mt][nt], af, bf[nt], acc[mt][nt]);
            }
        }

        // store next chunk into the idle stage (safe: last read at c-1, synced)
        if (c < 7) {
            const int nst = (c + 1) & 1;
            __nv_bfloat16* Asn = (__nv_bfloat16*)(sbuf + nst * STAGE_BYTES);
            __nv_bfloat16* Bsn = Asn + 10240 / 2;
            *(uint4*)(Asn + r0 * ASTRIDE + q0) = ra0;
            *(uint4*)(Asn + r1 * ASTRIDE + q1) = ra1;
            *(uint4*)(Bsn + r0 * ASTRIDE + q0) = rb0;
            *(uint4*)(Bsn + r1 * ASTRIDE + q1) = rb1;
        }
        __syncthreads();
    }

    // epilogue: reuse stage memory as per-warp staging (all compute done)
    float* ebuf = (float*)sbuf;
    float* eb = ebuf + wid * 256;
    const int er = lane >> 1, ec = (lane & 1) * 8;
#pragma unroll
    for (int mt = 0; mt < 4; mt++) {
#pragma unroll
        for (int nt = 0; nt < 2; nt++) {
            wmma::store_matrix_sync(eb, acc[mt][nt], 16, wmma::mem_row_major);
            __syncwarp();
            int grow = brow + warp_m * 64 + mt * 16 + er;
            int cl = warp_n * 32 + nt * 16 + ec;
            const float* e = eb + er * 16 + ec;
            __half2 h0 = __floats2half2_rn(msq_s[cl + 0] - 2.f * e[0],
                                           msq_s[cl + 1] - 2.f * e[1]);
            __half2 h1 = __floats2half2_rn(msq_s[cl + 2] - 2.f * e[2],
                                           msq_s[cl + 3] - 2.f * e[3]);
            __half2 h2 = __floats2half2_rn(msq_s[cl + 4] - 2.f * e[4],
                                           msq_s[cl + 5] - 2.f * e[5]);
            __half2 h3 = __floats2half2_rn(msq_s[cl + 6] - 2.f * e[6],
                                           msq_s[cl + 7] - 2.f * e[7]);
            uint4 pk;
            pk.x = *(uint32_t*)&h0; pk.y = *(uint32_t*)&h1;
            pk.z = *(uint32_t*)&h2; pk.w = *(uint32_t*)&h3;
            *(uint4*)&g_dist[(size_t)grow * M + bcol + cl] = pk;
            __syncwarp();
        }
    }
}

// ---------------------------------------------------------------------------
// Kernel 4: warp-per-row, dist rows streamed directly from gmem.
// Sample stats -> threshold filter (both-sided retry) -> top-32 via
// __reduce_min_sync -> BATCHED coalesced exact fp32 rescore (MLP 16) ->
// exact top-k -> softmax -> gather. 4 rows per 128-thread block.
// ---------------------------------------------------------------------------
__global__ __launch_bounds__(128)
void topk_kernel(const float* __restrict__ Mem, const int* __restrict__ kp,
                 float* __restrict__ out, int M, int D) {
    __shared__ float sh_q[RPB * DN];         // 4 KB
    __shared__ uint32_t ckey[RPB][CAPB];     // 8 KB
    __shared__ int ccnt[RPB];
    __shared__ int scand[RPB][NCAND];
    __shared__ float cd[RPB][NCAND];
    __shared__ float swt[RPB][MAXK];
    __shared__ int ssel[RPB][MAXK];

    const int tid = threadIdx.x, lane = tid & 31, w = tid >> 5;
    const int b0 = blockIdx.x * RPB;
    int k = kp[0];
    if (k < 1) k = 1;
    if (k > MAXK) k = MAXK;

    // Phase A: q rows to smem (used by rescore)
    {
        const float4* qsrc = (const float4*)(g_q + (size_t)b0 * DN);
        float4* qdst = (float4*)sh_q;
        for (int i = tid; i < RPB * DN / 4; i += 128) qdst[i] = qsrc[i];
    }
    __syncthreads();

    const uint4* drow4 = (const uint4*)(g_dist + (size_t)(b0 + w) * MN);

    // Phase B: per-warp sample stats (256 elems, coalesced) -> thr = mu-2sg
    float s1 = 0.f, s2 = 0.f;
    {
        uint4 pk = drow4[lane];
        const __half2* hp = (const __half2*)&pk;
#pragma unroll
        for (int e = 0; e < 4; e++) {
            float2 f = __half22float2(hp[e]);
            s1 += f.x + f.y; s2 += f.x * f.x + f.y * f.y;
        }
    }
#pragma unroll
    for (int off = 16; off; off >>= 1) {
        s1 += __shfl_xor_sync(0xffffffffu, s1, off);
        s2 += __shfl_xor_sync(0xffffffffu, s2, off);
    }
    float mu = s1 * (1.f / 256.f);
    float sg = sqrtf(fmaxf(s2 * (1.f / 256.f) - mu * mu, 0.f));
    sg = fmaxf(sg, fabsf(mu) * 1e-4f + 1e-6f);
    float thr = mu - 2.f * sg;

    // Phase C: threshold filter straight from gmem (coalesced uint4).
    int cnt = 0;
    for (int attempt = 0; attempt < 10; attempt++) {
        __half thrh = __float2half_ru(thr);
        if (lane == 0) ccnt[w] = 0;
        __syncwarp();
#pragma unroll 8
        for (int j = 0; j < 16; j++) {
            int gi = j * 32 + lane;
            uint4 pk = drow4[gi];
            __half2 a = *(__half2*)&pk.x, b = *(__half2*)&pk.y;
            __half2 c2 = *(__half2*)&pk.z, d2 = *(__half2*)&pk.w;
            __half2 m2 = __hmin2(__hmin2(a, b), __hmin2(c2, d2));
            __half mn = __hmin(__low2half(m2), __high2half(m2));
            if (__hlt(mn, thrh)) {
                const __half* hp = (const __half*)&pk;
                int base = gi * 8;
#pragma unroll
                for (int e = 0; e < 8; e++) {
                    __half h = hp[e];
                    if (__hlt(h, thrh)) {
                        unsigned short ub = __half_as_ushort(h);
                        uint32_t o = (ub & 0x8000u) ? (uint32_t)((~ub) & 0xFFFFu)
                                                    : (uint32_t)(ub | 0x8000u);
                        uint32_t key = (o << 12) | (uint32_t)(base + e);
                        int pos = atomicAdd(&ccnt[w], 1);
                        if (pos < CAPB) ckey[w][pos] = key;
                    }
                }
            }
        }
        __syncwarp();
        cnt = ccnt[w];
        if (cnt >= NCAND && cnt <= CAPB) break;
        thr += (cnt < NCAND) ? 0.5f * sg : -0.5f * sg;
        __syncwarp();
    }
    if (cnt > CAPB) cnt = CAPB;

    // Phase D: top-32 keys via warp redux (keys unique -> deterministic)
    {
        uint32_t lv[CAPB / 32];
#pragma unroll
        for (int j = 0; j < CAPB / 32; j++) {
            int s = lane + 32 * j;
            lv[j] = (s < cnt) ? ckey[w][s] : 0xFFFFFFFFu;
        }
        uint32_t lmin = 0xFFFFFFFFu;
#pragma unroll
        for (int j = 0; j < CAPB / 32; j++) lmin = min(lmin, lv[j]);
        for (int it = 0; it < NCAND; it++) {
            uint32_t g = __reduce_min_sync(0xffffffffu, lmin);
            if (lane == 0) scand[w][it] = (int)(g & 0xFFFu);
            unsigned bal = __ballot_sync(0xffffffffu, lmin == g);
            int wl = __ffs((int)bal) - 1;
            if (lane == wl) {
#pragma unroll
                for (int j = 0; j < CAPB / 32; j++)
                    if (lv[j] == g) lv[j] = 0xFFFFFFFFu;
                lmin = 0xFFFFFFFFu;
#pragma unroll
                for (int j = 0; j < CAPB / 32; j++) lmin = min(lmin, lv[j]);
            }
        }
    }
    __syncwarp();

    // Phase E: exact rescore — coalesced, BATCHED 8 candidates at a time
    // (16 ld.128 in flight, 8 interleaved shfl chains).
    {
        const float4* qp = (const float4*)(sh_q + w * DN);
        const float4 qa = qp[lane * 2], qb2 = qp[lane * 2 + 1];
#pragma unroll
        for (int cb = 0; cb < NCAND; cb += 8) {
            float4 ma[8], mb[8];
#pragma unroll
            for (int u = 0; u < 8; u++) {
                int midx = scand[w][cb + u];
                const float4* mp = (const float4*)(Mem + (size_t)midx * DN);
                ma[u] = mp[lane * 2];
                mb[u] = mp[lane * 2 + 1];
            }
            float dots[8];
#pragma unroll
            for (int u = 0; u < 8; u++)
                dots[u] = qa.x * ma[u].x + qa.y * ma[u].y + qa.z * ma[u].z + qa.w * ma[u].w
                        + qb2.x * mb[u].x + qb2.y * mb[u].y + qb2.z * mb[u].z + qb2.w * mb[u].w;
#pragma unroll
            for (int off = 16; off; off >>= 1)
#pragma unroll
                for (int u = 0; u < 8; u++)
                    dots[u] += __shfl_xor_sync(0xffffffffu, dots[u], off);
            if (lane == 0) {
#pragma unroll
                for (int u = 0; u < 8; u++)
                    cd[w][cb + u] = g_msq[scand[w][cb + u]] - 2.f * dots[u];
            }
        }
    }
    __syncwarp();

    // Phase F: exact top-k among 32, softmax(-dist), weighted gather
    {
        float v = cd[w][lane];
        for (int it = 0; it < k; it++) {
            float m = v; int s = lane;
#pragma unroll
            for (int off = 16; off; off >>= 1) {
                float m2 = __shfl_xor_sync(0xffffffffu, m, off);
                int s2 = __shfl_xor_sync(0xffffffffu, s, off);
                if (m2 < m || (m2 == m && s2 < s)) { m = m2; s = s2; }
            }
            if (lane == 0) { swt[w][it] = m; ssel[w][it] = scand[w][s]; }
            if (lane == s) v = BIGF;
        }
        __syncwarp();
        if (lane == 0) {
            float d0 = swt[w][0], ssum = 0.f;
            for (int i = 0; i < k; i++) {
                float e = expf(d0 - swt[w][i]);
                swt[w][i] = e; ssum += e;
            }
            float inv = 1.f / ssum;
            for (int i = 0; i < k; i++) swt[w][i] *= inv;
        }
        __syncwarp();

        const int d0 = lane * 8;
        float acc[8];
#pragma unroll
        for (int e = 0; e < 8; e++) acc[e] = 0.f;
#pragma unroll 4
        for (int i = 0; i < k; i++) {
            float wt = swt[w][i];
            const float4* mp = (const float4*)(Mem + (size_t)ssel[w][i] * DN + d0);
            float4 a = mp[0], bb = mp[1];
            acc[0] += wt * a.x;  acc[1] += wt * a.y;
            acc[2] += wt * a.z;  acc[3] += wt * a.w;
            acc[4] += wt * bb.x; acc[5] += wt * bb.y;
            acc[6] += wt * bb.z; acc[7] += wt * bb.w;
        }
        float4 o0 = make_float4(acc[0], acc[1], acc[2], acc[3]);
        float4 o1 = make_float4(acc[4], acc[5], acc[6], acc[7]);
        *(float4*)&out[(size_t)(b0 + w) * DN + d0] = o0;
        *(float4*)&out[(size_t)(b0 + w) * DN + d0 + 4] = o1;
    }
}

// ---------------------------------------------------------------------------
extern "C" void kernel_launch(void* const* d_in, const int* in_sizes, int n_in,
                              void* d_out, int out_size) {
    const float* h   = (const float*)d_in[0];
    const float* mem = (const float*)d_in[1];
    const float* Wq  = (const float*)d_in[2];
    const float* bq  = (const float*)d_in[3];
    const int*   kp  = (const int*)d_in[4];
    float* out = (float*)d_out;

    const int D  = in_sizes[3];
    const int Hd = in_sizes[2] / D;
    const int B  = in_sizes[0] / Hd;
    const int M  = in_sizes[1] / D;

    dim3 g1(D / 128, B / 128);
    qproj_kernel<<<g1, 256>>>(h, Wq, bq, B, Hd, D);
    msq_kernel<<<M, 64>>>(mem, D);
    dim3 g3(M / 128, B / 128);
    dist_wmma_kernel<<<g3, 256>>>(B, M, D);
    topk_kernel<<<B / RPB, 128>>>(mem, kp, out, M, D);
}